// round 1
// baseline (speedup 1.0000x reference)
#include <cuda_runtime.h>
#include <math.h>

#define BB 4
#define LL 1024
#define DMODEL 512
#define HH 8
#define NC 8
#define DK 64
#define LOG_AV (-4.605170185988091f)   // log(0.01)

// ---------------- scratch (device globals: no allocation allowed) ----------
__device__ float g_probs[2][BB][HH][LL][NC];   // side 0 = q, 1 = k
__device__ float g_q[BB][HH][LL][DK];
__device__ float g_k[BB][HH][LL][DK];
__device__ float g_v[BB][HH][LL][DK];
__device__ float g_ctx[BB][LL][DMODEL];
__device__ float g_M[2][BB][HH][36];           // upper-tri of P^T P
__device__ float g_klsum[2][BB][HH];
__device__ float g_dq2[2][BB][HH];
__device__ float g_dm1[2][BB][HH];

// ---------------- zero accumulators (graph replays re-run this) -----------
__global__ void zero_kernel() {
    int i = threadIdx.x;
    float* pM = &g_M[0][0][0][0];
    for (int e = i; e < 2 * BB * HH * 36; e += 256) pM[e] = 0.f;
    float* pk = &g_klsum[0][0][0];
    float* pd = &g_dq2[0][0][0];
    float* pm = &g_dm1[0][0][0];
    for (int e = i; e < 2 * BB * HH; e += 256) { pk[e] = 0.f; pd[e] = 0.f; pm[e] = 0.f; }
}

// ---------------- clustering: probs + KL/div statistics -------------------
// grid: (64, 4) -> blockIdx.x = s*32 + b*8 + h, blockIdx.y = token chunk
// block: 256 threads, 1 token each
__global__ __launch_bounds__(256) void clustering_kernel(
    const float* __restrict__ qin, const float* __restrict__ kin,
    const float* __restrict__ mu, const float* __restrict__ logvar,
    const float* __restrict__ logprior)
{
    __shared__ float mu_s[NC][DK];
    __shared__ float iv_s[NC][DK];
    __shared__ float lvs_s[NC], ratio_s[NC], logp_s[NC], prior_s[NC];

    int bx = blockIdx.x;
    int s = bx >> 5;
    int rem = bx & 31;
    int b = rem >> 3;
    int h = rem & 7;
    int tid = threadIdx.x;
    int l = blockIdx.y * 256 + tid;

    // load cluster params for this head
    for (int idx = tid; idx < NC * DK; idx += 256) {
        int c = idx >> 6, d = idx & 63;
        float lv = logvar[(h * NC + c) * DK + d];
        mu_s[c][d] = mu[(h * NC + c) * DK + d];
        iv_s[c][d] = expf(-lv);
    }
    __syncthreads();
    if (tid < NC) {
        float ls = 0.f, rs = 0.f;
        const float avar = expf(LOG_AV);
        for (int d = 0; d < DK; d++) {
            ls += logvar[(h * NC + tid) * DK + d];
            rs += iv_s[tid][d];
        }
        lvs_s[tid] = ls;
        ratio_s[tid] = avar * rs;
    }
    if (tid == 0) {
        float mx = -1e30f;
        for (int c = 0; c < NC; c++) mx = fmaxf(mx, logprior[h * NC + c]);
        float ss = 0.f;
        for (int c = 0; c < NC; c++) ss += expf(logprior[h * NC + c] - mx);
        float lse = mx + logf(ss);
        for (int c = 0; c < NC; c++) {
            logp_s[c] = logprior[h * NC + c] - lse;
            prior_s[c] = expf(logp_s[c]);
        }
    }
    __syncthreads();

    const float* src = (s == 0) ? qin : kin;
    const float* xr = src + ((size_t)b * LL + l) * DMODEL + h * DK;

    float x[DK];
#pragma unroll
    for (int d = 0; d < DK; d++) x[d] = xr[d];

    float mse[NC], logit[NC];
#pragma unroll
    for (int c = 0; c < NC; c++) {
        float a = 0.f;
#pragma unroll
        for (int d = 0; d < DK; d++) {
            float t = x[d] - mu_s[c][d];
            a = fmaf(t * t, iv_s[c][d], a);
        }
        mse[c] = a;
        logit[c] = -0.5f * a - 0.5f * lvs_s[c] + logp_s[c];
    }
    float m = logit[0];
#pragma unroll
    for (int c = 1; c < NC; c++) m = fmaxf(m, logit[c]);
    float p[NC];
    float Zl = 0.f;
#pragma unroll
    for (int c = 0; c < NC; c++) { p[c] = expf(logit[c] - m); Zl += p[c]; }
    float lz = logf(Zl);
    float inv = 1.f / Zl;

    float t1 = 0.f;
#pragma unroll
    for (int c = 0; c < NC; c++)
        t1 += prior_s[c] * (logp_s[c] - (logit[c] - m - lz));
#pragma unroll
    for (int c = 0; c < NC; c++) p[c] *= inv;
    float t2 = 0.f;
#pragma unroll
    for (int c = 0; c < NC; c++)
        t2 += p[c] * (mse[c] + ratio_s[c] + lvs_s[c]);
    float klloc = t1 + 0.5f * t2;

    float dq = 0.f;
#pragma unroll
    for (int c = 0; c < NC; c++) dq = fmaf(p[c], p[c], dq);
    float dq2loc = dq * dq;
    float dm1loc = (dq - 1.f) * (dq - 1.f);

    float Ml[36];
    {
        int e = 0;
#pragma unroll
        for (int c = 0; c < NC; c++)
#pragma unroll
            for (int c2 = c; c2 < NC; c2++) Ml[e++] = p[c] * p[c2];
    }
    // write probs
#pragma unroll
    for (int c = 0; c < NC; c++) g_probs[s][b][h][l][c] = p[c];

    // warp-reduce then atomic
#pragma unroll
    for (int e = 0; e < 36; e++) {
        float v = Ml[e];
        v += __shfl_xor_sync(0xffffffffu, v, 16);
        v += __shfl_xor_sync(0xffffffffu, v, 8);
        v += __shfl_xor_sync(0xffffffffu, v, 4);
        v += __shfl_xor_sync(0xffffffffu, v, 2);
        v += __shfl_xor_sync(0xffffffffu, v, 1);
        if ((tid & 31) == 0) atomicAdd(&g_M[s][b][h][e], v);
    }
    float v3[3] = { klloc, dq2loc, dm1loc };
    float* dsts[3] = { &g_klsum[s][b][h], &g_dq2[s][b][h], &g_dm1[s][b][h] };
#pragma unroll
    for (int e = 0; e < 3; e++) {
        float v = v3[e];
        v += __shfl_xor_sync(0xffffffffu, v, 16);
        v += __shfl_xor_sync(0xffffffffu, v, 8);
        v += __shfl_xor_sync(0xffffffffu, v, 4);
        v += __shfl_xor_sync(0xffffffffu, v, 2);
        v += __shfl_xor_sync(0xffffffffu, v, 1);
        if ((tid & 31) == 0) atomicAdd(dsts[e], v);
    }
}

// ---------------- GEMM: C = A(4096x512) * W^T (W is [N,K]=[512,512]) ------
// out_mode: 0/1/2 -> g_q/g_k/g_v (head layout, scaled), 3 -> flat out
// a_sel: 0 -> A param, 1 -> g_ctx
__global__ __launch_bounds__(256) void gemm_kernel(
    const float* __restrict__ A, int a_sel,
    const float* __restrict__ W, const float* __restrict__ bias,
    float scale, int out_mode, float* __restrict__ outp)
{
    __shared__ float As[64][17];
    __shared__ float Ws[64][17];

    const float* Ap = a_sel ? &g_ctx[0][0][0] : A;

    int tid = threadIdx.x;
    int tx = tid & 15, ty = tid >> 4;
    int m0 = blockIdx.y * 64, n0 = blockIdx.x * 64;
    int lrow = tid >> 2, lk = (tid & 3) << 2;

    float acc[4][4];
#pragma unroll
    for (int i = 0; i < 4; i++)
#pragma unroll
        for (int j = 0; j < 4; j++) acc[i][j] = 0.f;

    for (int k0 = 0; k0 < 512; k0 += 16) {
        float4 av = *(const float4*)&Ap[(size_t)(m0 + lrow) * 512 + k0 + lk];
        float4 wv = *(const float4*)&W[(size_t)(n0 + lrow) * 512 + k0 + lk];
        __syncthreads();
        As[lrow][lk] = av.x; As[lrow][lk + 1] = av.y; As[lrow][lk + 2] = av.z; As[lrow][lk + 3] = av.w;
        Ws[lrow][lk] = wv.x; Ws[lrow][lk + 1] = wv.y; Ws[lrow][lk + 2] = wv.z; Ws[lrow][lk + 3] = wv.w;
        __syncthreads();
#pragma unroll
        for (int kk = 0; kk < 16; kk++) {
            float a[4], w[4];
#pragma unroll
            for (int i = 0; i < 4; i++) a[i] = As[ty * 4 + i][kk];
#pragma unroll
            for (int j = 0; j < 4; j++) w[j] = Ws[tx * 4 + j][kk];
#pragma unroll
            for (int i = 0; i < 4; i++)
#pragma unroll
                for (int j = 0; j < 4; j++) acc[i][j] = fmaf(a[i], w[j], acc[i][j]);
        }
    }

#pragma unroll
    for (int i = 0; i < 4; i++) {
        int row = m0 + ty * 4 + i;
#pragma unroll
        for (int j = 0; j < 4; j++) {
            int col = n0 + tx * 4 + j;
            float v = (acc[i][j] + bias[col]) * scale;
            if (out_mode == 3) {
                outp[(size_t)row * 512 + col] = v;
            } else {
                int bb = row >> 10, l = row & 1023;
                int hh = col >> 6, dd = col & 63;
                float* dst = (out_mode == 0) ? &g_q[0][0][0][0]
                           : (out_mode == 1) ? &g_k[0][0][0][0]
                                             : &g_v[0][0][0][0];
                dst[(((size_t)(bb * HH + hh)) * LL + l) * DK + dd] = v;
            }
        }
    }
}

// ---------------- fused attention (flash-style) ---------------------------
// grid (B*H, L/32), block 128: 32 q-rows x 4 lanes/row; k-tile 64
__global__ __launch_bounds__(128) void attn_kernel(const float* __restrict__ pm)
{
    __shared__ float Qs[32 * 65];
    __shared__ float KP[64 * 68];   // K^T during S-phase, P during PV-phase
    __shared__ float Vs[64 * 68];
    __shared__ float pks[64 * 8];
    __shared__ float padk[64];

    int bh = blockIdx.x;
    int b = bh >> 3, h = bh & 7;
    int q0 = blockIdx.y * 32;
    int tid = threadIdx.x;
    int r = tid >> 2, tc = tid & 3;

    // load Q tile (32x64)
    for (int idx = tid; idx < 32 * 16; idx += 128) {
        int rr = idx >> 4; int dc = (idx & 15) << 2;
        float4 v = *(const float4*)&g_q[b][h][q0 + rr][dc];
        Qs[rr * 65 + dc] = v.x; Qs[rr * 65 + dc + 1] = v.y;
        Qs[rr * 65 + dc + 2] = v.z; Qs[rr * 65 + dc + 3] = v.w;
    }
    float pq[NC];
#pragma unroll
    for (int c = 0; c < NC; c++) pq[c] = g_probs[0][b][h][q0 + r][c];

    float o[16];
#pragma unroll
    for (int e = 0; e < 16; e++) o[e] = 0.f;
    float m = -1e30f, Z = 0.f;
    __syncthreads();

    for (int t = 0; t < 16; t++) {
        int k0 = t * 64;
        // load K^T (transposed), V, probs_k, padding
        for (int idx = tid; idx < 64 * 16; idx += 128) {
            int kk = idx >> 4; int dc = (idx & 15) << 2;
            float4 kv = *(const float4*)&g_k[b][h][k0 + kk][dc];
            KP[(dc + 0) * 68 + kk] = kv.x;
            KP[(dc + 1) * 68 + kk] = kv.y;
            KP[(dc + 2) * 68 + kk] = kv.z;
            KP[(dc + 3) * 68 + kk] = kv.w;
            float4 vv = *(const float4*)&g_v[b][h][k0 + kk][dc];
            *(float4*)&Vs[kk * 68 + dc] = vv;
        }
        {
            const float* pkbase = &g_probs[1][b][h][k0][0];
            for (int idx = tid; idx < 512; idx += 128) pks[idx] = pkbase[idx];
            if (tid < 64) padk[tid] = pm[(size_t)b * LL + k0 + tid];
        }
        __syncthreads();

        // scores for this thread's 16 k columns: k = tc*4 + jj*16 + j
        float acc[16], u[16];
#pragma unroll
        for (int jj = 0; jj < 4; jj++)
#pragma unroll
            for (int j = 0; j < 4; j++) {
                int e = jj * 4 + j;
                int kk = tc * 4 + jj * 16 + j;
                float sim = 0.f;
#pragma unroll
                for (int c = 0; c < NC; c++) sim = fmaf(pq[c], pks[kk * 8 + c], sim);
                float cm = 1.f - sim + padk[kk];
                cm = fminf(fmaxf(cm, 0.f), 1.f);
                u[e] = 1.f - cm;
                acc[e] = -10000.f * cm;
            }
#pragma unroll 8
        for (int d = 0; d < 64; d++) {
            float qd = Qs[r * 65 + d];
#pragma unroll
            for (int jj = 0; jj < 4; jj++) {
                float4 kv = *(const float4*)&KP[d * 68 + tc * 4 + jj * 16];
                acc[jj * 4 + 0] = fmaf(qd, kv.x, acc[jj * 4 + 0]);
                acc[jj * 4 + 1] = fmaf(qd, kv.y, acc[jj * 4 + 1]);
                acc[jj * 4 + 2] = fmaf(qd, kv.z, acc[jj * 4 + 2]);
                acc[jj * 4 + 3] = fmaf(qd, kv.w, acc[jj * 4 + 3]);
            }
        }

        // online softmax (row group of 4 lanes)
        float tmax = acc[0];
#pragma unroll
        for (int e = 1; e < 16; e++) tmax = fmaxf(tmax, acc[e]);
        tmax = fmaxf(tmax, __shfl_xor_sync(0xffffffffu, tmax, 1));
        tmax = fmaxf(tmax, __shfl_xor_sync(0xffffffffu, tmax, 2));
        float mn = fmaxf(m, tmax);
        float corr = __expf(m - mn);
        Z *= corr;
#pragma unroll
        for (int e = 0; e < 16; e++) o[e] *= corr;
        float zl = 0.f;
        float pe[16];
#pragma unroll
        for (int e = 0; e < 16; e++) {
            float pp = __expf(acc[e] - mn);
            zl += pp;
            pe[e] = pp * u[e];
        }
        zl += __shfl_xor_sync(0xffffffffu, zl, 1);
        zl += __shfl_xor_sync(0xffffffffu, zl, 2);
        Z += zl;
        m = mn;

        __syncthreads();   // done reading KP as K^T
#pragma unroll
        for (int jj = 0; jj < 4; jj++)
#pragma unroll
            for (int j = 0; j < 4; j++)
                KP[r * 68 + tc * 4 + jj * 16 + j] = pe[jj * 4 + j];
        __syncthreads();

        // PV
#pragma unroll 4
        for (int kk = 0; kk < 64; kk++) {
            float pp = KP[r * 68 + kk];
#pragma unroll
            for (int jj = 0; jj < 4; jj++) {
                float4 vv = *(const float4*)&Vs[kk * 68 + tc * 4 + jj * 16];
                o[jj * 4 + 0] = fmaf(pp, vv.x, o[jj * 4 + 0]);
                o[jj * 4 + 1] = fmaf(pp, vv.y, o[jj * 4 + 1]);
                o[jj * 4 + 2] = fmaf(pp, vv.z, o[jj * 4 + 2]);
                o[jj * 4 + 3] = fmaf(pp, vv.w, o[jj * 4 + 3]);
            }
        }
        __syncthreads();   // before next tile load overwrites KP/Vs
    }

    float iz = 1.f / Z;
#pragma unroll
    for (int jj = 0; jj < 4; jj++) {
        float4 ov;
        ov.x = o[jj * 4 + 0] * iz;
        ov.y = o[jj * 4 + 1] * iz;
        ov.z = o[jj * 4 + 2] * iz;
        ov.w = o[jj * 4 + 3] * iz;
        *(float4*)&g_ctx[b][q0 + r][h * DK + tc * 4 + jj * 16] = ov;
    }
}

// ---------------- finalize: kl_loss[b], div_loss[b] -> tail of d_out ------
__global__ void finalize_kernel(float* __restrict__ out, int out_size)
{
    int b = threadIdx.x;
    if (b >= BB) return;
    float kl = 0.f;
    for (int s = 0; s < 2; s++)
        for (int h = 0; h < HH; h++) kl += g_klsum[s][b][h];
    const float c3 = -0.5f * (1.0f + LOG_AV) * (float)DK;
    float kl_total = kl / (float)(HH * LL) + 2.f * c3;

    float dv = 0.f;
    for (int s = 0; s < 2; s++)
        for (int h = 0; h < HH; h++) {
            float frob = 0.f;
            int e = 0;
            for (int c = 0; c < NC; c++)
                for (int c2 = c; c2 < NC; c2++) {
                    float mv = g_M[s][b][h][e++];
                    frob += (c2 == c) ? mv * mv : 2.f * mv * mv;
                }
            dv += 0.75f * (frob - g_dq2[s][b][h]) + 1.25f * g_dm1[s][b][h];
        }
    dv /= (float)HH * (float)LL * (float)LL;

    long base = (long)BB * LL * DMODEL;
    if (out_size >= base + 2 * BB) {
        out[base + b] = kl_total;
        out[base + BB + b] = dv;
    }
}

// ---------------- launch ---------------------------------------------------
extern "C" void kernel_launch(void* const* d_in, const int* in_sizes, int n_in,
                              void* d_out, int out_size)
{
    const float* query  = (const float*)d_in[0];
    const float* key    = (const float*)d_in[1];
    const float* value  = (const float*)d_in[2];
    const float* pmask  = (const float*)d_in[3];
    const float* Wq = (const float*)d_in[4];
    const float* bq = (const float*)d_in[5];
    const float* Wk = (const float*)d_in[6];
    const float* bk = (const float*)d_in[7];
    const float* Wv = (const float*)d_in[8];
    const float* bv = (const float*)d_in[9];
    const float* Wo = (const float*)d_in[10];
    const float* bo = (const float*)d_in[11];
    const float* tok_mu = (const float*)d_in[12];
    const float* tok_lv = (const float*)d_in[13];
    const float* tok_lp = (const float*)d_in[14];
    float* outp = (float*)d_out;

    zero_kernel<<<1, 256>>>();
    clustering_kernel<<<dim3(2 * BB * HH, 4), 256>>>(query, key, tok_mu, tok_lv, tok_lp);

    gemm_kernel<<<dim3(8, 64), 256>>>(query, 0, Wq, bq, 0.125f, 0, nullptr);
    gemm_kernel<<<dim3(8, 64), 256>>>(key,   0, Wk, bk, 1.0f,   1, nullptr);
    gemm_kernel<<<dim3(8, 64), 256>>>(value, 0, Wv, bv, 1.0f,   2, nullptr);

    attn_kernel<<<dim3(BB * HH, LL / 32), 128>>>(pmask);

    gemm_kernel<<<dim3(8, 64), 256>>>(nullptr, 1, Wo, bo, 1.0f, 3, outp);
    finalize_kernel<<<1, 32>>>(outp, out_size);
}

// round 2
// speedup vs baseline: 3.6419x; 3.6419x over previous
#include <cuda_runtime.h>
#include <math.h>
#include <stdint.h>

#define BB 4
#define LL 1024
#define DMODEL 512
#define HH 8
#define NC 8
#define DK 64
#define LOG_AV (-4.605170185988091f)   // log(0.01)

// ---------------- scratch (device globals: no allocation allowed) ----------
__device__ float g_probs[2][BB][HH][LL][NC];   // side 0 = q, 1 = k
__device__ float g_q[BB][HH][LL][DK];
__device__ float g_k[BB][HH][LL][DK];
__device__ float g_v[BB][HH][LL][DK];
__device__ float g_ctx[BB][LL][DMODEL];
__device__ float g_M[2][BB][HH][36];           // upper-tri of P^T P
__device__ float g_klsum[2][BB][HH];
__device__ float g_dq2[2][BB][HH];
__device__ float g_dm1[2][BB][HH];

// ---------------- tf32 mma helpers ----------------------------------------
__device__ __forceinline__ uint32_t f2tf(float x) {
    uint32_t r;
    asm("cvt.rna.tf32.f32 %0, %1;" : "=r"(r) : "f"(x));
    return r;
}

__device__ __forceinline__ void mma8(float* c, const uint32_t* a, uint32_t b0, uint32_t b1) {
    asm volatile(
        "mma.sync.aligned.m16n8k8.row.col.f32.tf32.tf32.f32 "
        "{%0,%1,%2,%3}, {%4,%5,%6,%7}, {%8,%9}, {%0,%1,%2,%3};"
        : "+f"(c[0]), "+f"(c[1]), "+f"(c[2]), "+f"(c[3])
        : "r"(a[0]), "r"(a[1]), "r"(a[2]), "r"(a[3]), "r"(b0), "r"(b1));
}

// ---------------- zero accumulators (graph replays re-run this) -----------
__global__ void zero_kernel() {
    int i = threadIdx.x;
    float* pM = &g_M[0][0][0][0];
    for (int e = i; e < 2 * BB * HH * 36; e += 256) pM[e] = 0.f;
    float* pk = &g_klsum[0][0][0];
    float* pd = &g_dq2[0][0][0];
    float* pm = &g_dm1[0][0][0];
    for (int e = i; e < 2 * BB * HH; e += 256) { pk[e] = 0.f; pd[e] = 0.f; pm[e] = 0.f; }
}

// ---------------- clustering: probs + KL/div statistics -------------------
__global__ __launch_bounds__(256) void clustering_kernel(
    const float* __restrict__ qin, const float* __restrict__ kin,
    const float* __restrict__ mu, const float* __restrict__ logvar,
    const float* __restrict__ logprior)
{
    __shared__ float mu_s[NC][DK];
    __shared__ float iv_s[NC][DK];
    __shared__ float lvs_s[NC], ratio_s[NC], logp_s[NC], prior_s[NC];

    int bx = blockIdx.x;
    int s = bx >> 5;
    int rem = bx & 31;
    int b = rem >> 3;
    int h = rem & 7;
    int tid = threadIdx.x;
    int l = blockIdx.y * 256 + tid;

    for (int idx = tid; idx < NC * DK; idx += 256) {
        int c = idx >> 6, d = idx & 63;
        float lv = logvar[(h * NC + c) * DK + d];
        mu_s[c][d] = mu[(h * NC + c) * DK + d];
        iv_s[c][d] = expf(-lv);
    }
    __syncthreads();
    if (tid < NC) {
        float ls = 0.f, rs = 0.f;
        const float avar = expf(LOG_AV);
        for (int d = 0; d < DK; d++) {
            ls += logvar[(h * NC + tid) * DK + d];
            rs += iv_s[tid][d];
        }
        lvs_s[tid] = ls;
        ratio_s[tid] = avar * rs;
    }
    if (tid == 0) {
        float mx = -1e30f;
        for (int c = 0; c < NC; c++) mx = fmaxf(mx, logprior[h * NC + c]);
        float ss = 0.f;
        for (int c = 0; c < NC; c++) ss += expf(logprior[h * NC + c] - mx);
        float lse = mx + logf(ss);
        for (int c = 0; c < NC; c++) {
            logp_s[c] = logprior[h * NC + c] - lse;
            prior_s[c] = expf(logp_s[c]);
        }
    }
    __syncthreads();

    const float* src = (s == 0) ? qin : kin;
    const float* xr = src + ((size_t)b * LL + l) * DMODEL + h * DK;

    float x[DK];
#pragma unroll
    for (int d = 0; d < DK; d++) x[d] = xr[d];

    float mse[NC], logit[NC];
#pragma unroll
    for (int c = 0; c < NC; c++) {
        float a = 0.f;
#pragma unroll
        for (int d = 0; d < DK; d++) {
            float t = x[d] - mu_s[c][d];
            a = fmaf(t * t, iv_s[c][d], a);
        }
        mse[c] = a;
        logit[c] = -0.5f * a - 0.5f * lvs_s[c] + logp_s[c];
    }
    float m = logit[0];
#pragma unroll
    for (int c = 1; c < NC; c++) m = fmaxf(m, logit[c]);
    float p[NC];
    float Zl = 0.f;
#pragma unroll
    for (int c = 0; c < NC; c++) { p[c] = expf(logit[c] - m); Zl += p[c]; }
    float lz = logf(Zl);
    float inv = 1.f / Zl;

    float t1 = 0.f;
#pragma unroll
    for (int c = 0; c < NC; c++)
        t1 += prior_s[c] * (logp_s[c] - (logit[c] - m - lz));
#pragma unroll
    for (int c = 0; c < NC; c++) p[c] *= inv;
    float t2 = 0.f;
#pragma unroll
    for (int c = 0; c < NC; c++)
        t2 += p[c] * (mse[c] + ratio_s[c] + lvs_s[c]);
    float klloc = t1 + 0.5f * t2;

    float dq = 0.f;
#pragma unroll
    for (int c = 0; c < NC; c++) dq = fmaf(p[c], p[c], dq);
    float dq2loc = dq * dq;
    float dm1loc = (dq - 1.f) * (dq - 1.f);

    float Ml[36];
    {
        int e = 0;
#pragma unroll
        for (int c = 0; c < NC; c++)
#pragma unroll
            for (int c2 = c; c2 < NC; c2++) Ml[e++] = p[c] * p[c2];
    }
#pragma unroll
    for (int c = 0; c < NC; c++) g_probs[s][b][h][l][c] = p[c];

#pragma unroll
    for (int e = 0; e < 36; e++) {
        float v = Ml[e];
        v += __shfl_xor_sync(0xffffffffu, v, 16);
        v += __shfl_xor_sync(0xffffffffu, v, 8);
        v += __shfl_xor_sync(0xffffffffu, v, 4);
        v += __shfl_xor_sync(0xffffffffu, v, 2);
        v += __shfl_xor_sync(0xffffffffu, v, 1);
        if ((tid & 31) == 0) atomicAdd(&g_M[s][b][h][e], v);
    }
    float v3[3] = { klloc, dq2loc, dm1loc };
    float* dsts[3] = { &g_klsum[s][b][h], &g_dq2[s][b][h], &g_dm1[s][b][h] };
#pragma unroll
    for (int e = 0; e < 3; e++) {
        float v = v3[e];
        v += __shfl_xor_sync(0xffffffffu, v, 16);
        v += __shfl_xor_sync(0xffffffffu, v, 8);
        v += __shfl_xor_sync(0xffffffffu, v, 4);
        v += __shfl_xor_sync(0xffffffffu, v, 2);
        v += __shfl_xor_sync(0xffffffffu, v, 1);
        if ((tid & 31) == 0) atomicAdd(dsts[e], v);
    }
}

// ---------------- tf32 GEMM: C = A(4096x512) * W^T ------------------------
// CTA tile 128x128, 8 warps (4 m-slices x 2 n-slices), warp tile 32x64.
// out_mode: 0/1/2 -> g_q/g_k/g_v (head layout, scaled), 3 -> flat out
#define GSTR 36
__global__ __launch_bounds__(256) void gemm_tf32(
    const float* __restrict__ A, int a_sel,
    const float* __restrict__ W, const float* __restrict__ bias,
    float scale, int out_mode, float* __restrict__ outp)
{
    __shared__ uint32_t As[128 * GSTR];
    __shared__ uint32_t Bs[128 * GSTR];

    const float* Ap = a_sel ? &g_ctx[0][0][0] : A;

    int tid = threadIdx.x;
    int lane = tid & 31, wid = tid >> 5;
    int g = lane >> 2, q = lane & 3;
    int wm = wid & 3, wn = wid >> 2;
    int m0 = blockIdx.y * 128, n0 = blockIdx.x * 128;

    int ldr = tid >> 3;            // 0..31
    int ldc = (tid & 7) << 2;      // 0..28

    float4 abuf[4], bbuf[4];
    float acc[2][8][4];
#pragma unroll
    for (int mt = 0; mt < 2; mt++)
#pragma unroll
        for (int nt = 0; nt < 8; nt++)
#pragma unroll
            for (int s = 0; s < 4; s++) acc[mt][nt][s] = 0.f;

    // preload chunk 0
#pragma unroll
    for (int i = 0; i < 4; i++) {
        abuf[i] = *(const float4*)&Ap[(size_t)(m0 + ldr + i * 32) * 512 + ldc];
        bbuf[i] = *(const float4*)&W[(size_t)(n0 + ldr + i * 32) * 512 + ldc];
    }

    for (int kc = 0; kc < 16; kc++) {
        __syncthreads();
#pragma unroll
        for (int i = 0; i < 4; i++) {
            int row = ldr + i * 32;
            uint4 av, bv;
            av.x = f2tf(abuf[i].x); av.y = f2tf(abuf[i].y);
            av.z = f2tf(abuf[i].z); av.w = f2tf(abuf[i].w);
            bv.x = f2tf(bbuf[i].x); bv.y = f2tf(bbuf[i].y);
            bv.z = f2tf(bbuf[i].z); bv.w = f2tf(bbuf[i].w);
            *(uint4*)&As[row * GSTR + ldc] = av;
            *(uint4*)&Bs[row * GSTR + ldc] = bv;
        }
        __syncthreads();
        if (kc < 15) {
            int k0 = (kc + 1) * 32;
#pragma unroll
            for (int i = 0; i < 4; i++) {
                abuf[i] = *(const float4*)&Ap[(size_t)(m0 + ldr + i * 32) * 512 + k0 + ldc];
                bbuf[i] = *(const float4*)&W[(size_t)(n0 + ldr + i * 32) * 512 + k0 + ldc];
            }
        }
#pragma unroll
        for (int ks = 0; ks < 4; ks++) {
            uint32_t a[2][4];
#pragma unroll
            for (int mt = 0; mt < 2; mt++) {
                int mr = wm * 32 + mt * 16;
                a[mt][0] = As[(mr + g) * GSTR + ks * 8 + q];
                a[mt][1] = As[(mr + g + 8) * GSTR + ks * 8 + q];
                a[mt][2] = As[(mr + g) * GSTR + ks * 8 + q + 4];
                a[mt][3] = As[(mr + g + 8) * GSTR + ks * 8 + q + 4];
            }
#pragma unroll
            for (int nt = 0; nt < 8; nt++) {
                uint32_t b0 = Bs[(wn * 64 + nt * 8 + g) * GSTR + ks * 8 + q];
                uint32_t b1 = Bs[(wn * 64 + nt * 8 + g) * GSTR + ks * 8 + q + 4];
                mma8(acc[0][nt], a[0], b0, b1);
                mma8(acc[1][nt], a[1], b0, b1);
            }
        }
    }

    // epilogue
#pragma unroll
    for (int mt = 0; mt < 2; mt++) {
#pragma unroll
        for (int nt = 0; nt < 8; nt++) {
#pragma unroll
            for (int s = 0; s < 4; s++) {
                int row = m0 + wm * 32 + mt * 16 + g + ((s >= 2) ? 8 : 0);
                int col = n0 + wn * 64 + nt * 8 + 2 * q + (s & 1);
                float v = (acc[mt][nt][s] + bias[col]) * scale;
                if (out_mode == 3) {
                    outp[(size_t)row * 512 + col] = v;
                } else {
                    int bb = row >> 10, l = row & 1023;
                    int hh = col >> 6, dd = col & 63;
                    float* dst = (out_mode == 0) ? &g_q[0][0][0][0]
                               : (out_mode == 1) ? &g_k[0][0][0][0]
                                                 : &g_v[0][0][0][0];
                    dst[(((size_t)(bb * HH + hh)) * LL + l) * DK + dd] = v;
                }
            }
        }
    }
}

// ---------------- fused flash attention with tf32 mma ---------------------
// grid (B*H, L/64), block 128 (4 warps x 16 q-rows); k-tile 64.
#define KSTR 68
#define VSTR 72
__global__ __launch_bounds__(128) void attn_tf32(const float* __restrict__ pm)
{
    __shared__ uint32_t Ks[64 * KSTR];
    __shared__ uint32_t Vs[64 * VSTR];
    __shared__ float pks[64 * 8];
    __shared__ float padk[64];

    int bh = blockIdx.x;
    int b = bh >> 3, h = bh & 7;
    int q0 = blockIdx.y * 64;
    int tid = threadIdx.x;
    int lane = tid & 31, w = tid >> 5;
    int g = lane >> 2, q = lane & 3;
    int r0 = q0 + w * 16 + g;
    int r1 = r0 + 8;

    // preload Q fragments (tf32) and pq rows
    uint32_t qa[8][4];
#pragma unroll
    for (int ks = 0; ks < 8; ks++) {
        qa[ks][0] = f2tf(g_q[b][h][r0][ks * 8 + q]);
        qa[ks][1] = f2tf(g_q[b][h][r1][ks * 8 + q]);
        qa[ks][2] = f2tf(g_q[b][h][r0][ks * 8 + q + 4]);
        qa[ks][3] = f2tf(g_q[b][h][r1][ks * 8 + q + 4]);
    }
    float pq0[8], pq1[8];
#pragma unroll
    for (int c = 0; c < NC; c++) {
        pq0[c] = g_probs[0][b][h][r0][c];
        pq1[c] = g_probs[0][b][h][r1][c];
    }

    float accO[8][4];
#pragma unroll
    for (int nt = 0; nt < 8; nt++)
#pragma unroll
        for (int s = 0; s < 4; s++) accO[nt][s] = 0.f;
    float mrow0 = -1e30f, mrow1 = -1e30f, Z0 = 0.f, Z1 = 0.f;

    for (int t = 0; t < 16; t++) {
        int k0 = t * 64;
        // fill K/V tiles (tf32) + pk + pad
        for (int idx = tid; idx < 64 * 16; idx += 128) {
            int kk = idx >> 4, dc = (idx & 15) << 2;
            float4 kv = *(const float4*)&g_k[b][h][k0 + kk][dc];
            float4 vv = *(const float4*)&g_v[b][h][k0 + kk][dc];
            uint4 ku, vu;
            ku.x = f2tf(kv.x); ku.y = f2tf(kv.y); ku.z = f2tf(kv.z); ku.w = f2tf(kv.w);
            vu.x = f2tf(vv.x); vu.y = f2tf(vv.y); vu.z = f2tf(vv.z); vu.w = f2tf(vv.w);
            *(uint4*)&Ks[kk * KSTR + dc] = ku;
            *(uint4*)&Vs[kk * VSTR + dc] = vu;
        }
        {
            const float* pkbase = &g_probs[1][b][h][k0][0];
            if (tid < 128) *(float4*)&pks[tid * 4] = *(const float4*)&pkbase[tid * 4];
            if (tid < 64) padk[tid] = pm[(size_t)b * LL + k0 + tid];
        }
        __syncthreads();

        // bias = -10000*cmask (exact fp32); u kept as bias copy
        float accS[8][4], u[8][4];
#pragma unroll
        for (int nt = 0; nt < 8; nt++) {
#pragma unroll
            for (int j = 0; j < 2; j++) {
                int c = nt * 8 + 2 * q + j;
                float4 pA = *(const float4*)&pks[c * 8];
                float4 pB = *(const float4*)&pks[c * 8 + 4];
                float s0 = pq0[0] * pA.x + pq0[1] * pA.y + pq0[2] * pA.z + pq0[3] * pA.w
                         + pq0[4] * pB.x + pq0[5] * pB.y + pq0[6] * pB.z + pq0[7] * pB.w;
                float s1 = pq1[0] * pA.x + pq1[1] * pA.y + pq1[2] * pA.z + pq1[3] * pA.w
                         + pq1[4] * pB.x + pq1[5] * pB.y + pq1[6] * pB.z + pq1[7] * pB.w;
                float pd = padk[c];
                float cm0 = fminf(fmaxf(1.f - s0 + pd, 0.f), 1.f);
                float cm1 = fminf(fmaxf(1.f - s1 + pd, 0.f), 1.f);
                accS[nt][j]     = -10000.f * cm0; u[nt][j]     = accS[nt][j];
                accS[nt][2 + j] = -10000.f * cm1; u[nt][2 + j] = accS[nt][2 + j];
            }
        }

        // S += Q * K^T
#pragma unroll
        for (int ks = 0; ks < 8; ks++) {
#pragma unroll
            for (int nt = 0; nt < 8; nt++) {
                uint32_t b0 = Ks[(nt * 8 + g) * KSTR + ks * 8 + q];
                uint32_t b1 = Ks[(nt * 8 + g) * KSTR + ks * 8 + q + 4];
                mma8(accS[nt], qa[ks], b0, b1);
            }
        }

        // online softmax (rows r0 and r1 independently)
        float t0 = accS[0][0], t1v = accS[0][2];
#pragma unroll
        for (int nt = 0; nt < 8; nt++) {
            t0 = fmaxf(t0, fmaxf(accS[nt][0], accS[nt][1]));
            t1v = fmaxf(t1v, fmaxf(accS[nt][2], accS[nt][3]));
        }
        t0 = fmaxf(t0, __shfl_xor_sync(0xffffffffu, t0, 1));
        t0 = fmaxf(t0, __shfl_xor_sync(0xffffffffu, t0, 2));
        t1v = fmaxf(t1v, __shfl_xor_sync(0xffffffffu, t1v, 1));
        t1v = fmaxf(t1v, __shfl_xor_sync(0xffffffffu, t1v, 2));
        float mn0 = fmaxf(mrow0, t0), mn1 = fmaxf(mrow1, t1v);
        float corr0 = __expf(mrow0 - mn0), corr1 = __expf(mrow1 - mn1);
        mrow0 = mn0; mrow1 = mn1;
        Z0 *= corr0; Z1 *= corr1;
#pragma unroll
        for (int nt = 0; nt < 8; nt++) {
            accO[nt][0] *= corr0; accO[nt][1] *= corr0;
            accO[nt][2] *= corr1; accO[nt][3] *= corr1;
        }
        float z0 = 0.f, z1 = 0.f;
#pragma unroll
        for (int nt = 0; nt < 8; nt++) {
            float e0 = __expf(accS[nt][0] - mn0);
            float e1 = __expf(accS[nt][1] - mn0);
            float e2 = __expf(accS[nt][2] - mn1);
            float e3 = __expf(accS[nt][3] - mn1);
            z0 += e0 + e1; z1 += e2 + e3;
            accS[nt][0] = e0 * (1.f + u[nt][0] * 1e-4f);
            accS[nt][1] = e1 * (1.f + u[nt][1] * 1e-4f);
            accS[nt][2] = e2 * (1.f + u[nt][2] * 1e-4f);
            accS[nt][3] = e3 * (1.f + u[nt][3] * 1e-4f);
        }
        Z0 += z0; Z1 += z1;

        // O += P * V : permute P C-frag -> A-frag via quad shuffles
        int srcA = (lane & ~3) | (q >> 1);
        int srcB = srcA + 2;
        bool odd = (q & 1);
#pragma unroll
        for (int kg = 0; kg < 8; kg++) {
            float x0 = __shfl_sync(0xffffffffu, accS[kg][0], srcA);
            float x1 = __shfl_sync(0xffffffffu, accS[kg][1], srcA);
            float x4 = __shfl_sync(0xffffffffu, accS[kg][0], srcB);
            float x5 = __shfl_sync(0xffffffffu, accS[kg][1], srcB);
            float y0 = __shfl_sync(0xffffffffu, accS[kg][2], srcA);
            float y1 = __shfl_sync(0xffffffffu, accS[kg][3], srcA);
            float y4 = __shfl_sync(0xffffffffu, accS[kg][2], srcB);
            float y5 = __shfl_sync(0xffffffffu, accS[kg][3], srcB);
            uint32_t a[4];
            a[0] = f2tf(odd ? x1 : x0);   // P[r0][8kg + q]
            a[1] = f2tf(odd ? y1 : y0);   // P[r1][8kg + q]
            a[2] = f2tf(odd ? x5 : x4);   // P[r0][8kg + q + 4]
            a[3] = f2tf(odd ? y5 : y4);   // P[r1][8kg + q + 4]
#pragma unroll
            for (int nt = 0; nt < 8; nt++) {
                uint32_t b0 = Vs[(kg * 8 + q) * VSTR + nt * 8 + g];
                uint32_t b1 = Vs[(kg * 8 + q + 4) * VSTR + nt * 8 + g];
                mma8(accO[nt], a, b0, b1);
            }
        }
        __syncthreads();
    }

    // finalize: divide by Z (quad-reduce partial sums), write g_ctx
    Z0 += __shfl_xor_sync(0xffffffffu, Z0, 1);
    Z0 += __shfl_xor_sync(0xffffffffu, Z0, 2);
    Z1 += __shfl_xor_sync(0xffffffffu, Z1, 1);
    Z1 += __shfl_xor_sync(0xffffffffu, Z1, 2);
    float iz0 = 1.f / Z0, iz1 = 1.f / Z1;
#pragma unroll
    for (int nt = 0; nt < 8; nt++) {
        float2 o0 = make_float2(accO[nt][0] * iz0, accO[nt][1] * iz0);
        float2 o1 = make_float2(accO[nt][2] * iz1, accO[nt][3] * iz1);
        *(float2*)&g_ctx[b][r0][h * DK + nt * 8 + 2 * q] = o0;
        *(float2*)&g_ctx[b][r1][h * DK + nt * 8 + 2 * q] = o1;
    }
}

// ---------------- finalize: kl_loss[b], div_loss[b] -> tail of d_out ------
__global__ void finalize_kernel(float* __restrict__ out, int out_size)
{
    int b = threadIdx.x;
    if (b >= BB) return;
    float kl = 0.f;
    for (int s = 0; s < 2; s++)
        for (int h = 0; h < HH; h++) kl += g_klsum[s][b][h];
    const float c3 = -0.5f * (1.0f + LOG_AV) * (float)DK;
    float kl_total = kl / (float)(HH * LL) + 2.f * c3;

    float dv = 0.f;
    for (int s = 0; s < 2; s++)
        for (int h = 0; h < HH; h++) {
            float frob = 0.f;
            int e = 0;
            for (int c = 0; c < NC; c++)
                for (int c2 = c; c2 < NC; c2++) {
                    float mv = g_M[s][b][h][e++];
                    frob += (c2 == c) ? mv * mv : 2.f * mv * mv;
                }
            dv += 0.75f * (frob - g_dq2[s][b][h]) + 1.25f * g_dm1[s][b][h];
        }
    dv /= (float)HH * (float)LL * (float)LL;

    long base = (long)BB * LL * DMODEL;
    if (out_size >= base + 2 * BB) {
        out[base + b] = kl_total;
        out[base + BB + b] = dv;
    }
}

// ---------------- launch ---------------------------------------------------
extern "C" void kernel_launch(void* const* d_in, const int* in_sizes, int n_in,
                              void* d_out, int out_size)
{
    const float* query  = (const float*)d_in[0];
    const float* key    = (const float*)d_in[1];
    const float* value  = (const float*)d_in[2];
    const float* pmask  = (const float*)d_in[3];
    const float* Wq = (const float*)d_in[4];
    const float* bq = (const float*)d_in[5];
    const float* Wk = (const float*)d_in[6];
    const float* bk = (const float*)d_in[7];
    const float* Wv = (const float*)d_in[8];
    const float* bv = (const float*)d_in[9];
    const float* Wo = (const float*)d_in[10];
    const float* bo = (const float*)d_in[11];
    const float* tok_mu = (const float*)d_in[12];
    const float* tok_lv = (const float*)d_in[13];
    const float* tok_lp = (const float*)d_in[14];
    float* outp = (float*)d_out;

    zero_kernel<<<1, 256>>>();
    clustering_kernel<<<dim3(2 * BB * HH, 4), 256>>>(query, key, tok_mu, tok_lv, tok_lp);

    gemm_tf32<<<dim3(4, 32), 256>>>(query, 0, Wq, bq, 0.125f, 0, nullptr);
    gemm_tf32<<<dim3(4, 32), 256>>>(key,   0, Wk, bk, 1.0f,   1, nullptr);
    gemm_tf32<<<dim3(4, 32), 256>>>(value, 0, Wv, bv, 1.0f,   2, nullptr);

    attn_tf32<<<dim3(BB * HH, LL / 64), 128>>>(pmask);

    gemm_tf32<<<dim3(4, 32), 256>>>(nullptr, 1, Wo, bo, 1.0f, 3, outp);
    finalize_kernel<<<1, 32>>>(outp, out_size);
}

// round 3
// speedup vs baseline: 4.0898x; 1.1230x over previous
#include <cuda_runtime.h>
#include <math.h>
#include <stdint.h>

#define BB 4
#define LL 1024
#define DMODEL 512
#define HH 8
#define NC 8
#define DK 64
#define LOG_AV (-4.605170185988091f)   // log(0.01)

// ---------------- scratch (device globals: no allocation allowed) ----------
__device__ __align__(256) float    g_probs[2][BB][HH][LL][NC]; // 0=q,1=k
__device__ __align__(256) uint32_t g_q[BB][HH][LL][DK];        // tf32 bits
__device__ __align__(256) uint32_t g_k[BB][HH][LL][DK];        // tf32 bits
__device__ __align__(256) uint32_t g_v[BB][HH][LL][DK];        // tf32 bits
__device__ __align__(256) float    g_ctx[BB][LL][DMODEL];
__device__ float g_M[2][BB][HH][36];
__device__ float g_klsum[2][BB][HH];
__device__ float g_dq2[2][BB][HH];
__device__ float g_dm1[2][BB][HH];

// ---------------- helpers ---------------------------------------------------
__device__ __forceinline__ uint32_t f2tf(float x) {
    uint32_t r;
    asm("cvt.rna.tf32.f32 %0, %1;" : "=r"(r) : "f"(x));
    return r;
}
__device__ __forceinline__ void mma8(float* c, const uint32_t* a, uint32_t b0, uint32_t b1) {
    asm volatile(
        "mma.sync.aligned.m16n8k8.row.col.f32.tf32.tf32.f32 "
        "{%0,%1,%2,%3}, {%4,%5,%6,%7}, {%8,%9}, {%0,%1,%2,%3};"
        : "+f"(c[0]), "+f"(c[1]), "+f"(c[2]), "+f"(c[3])
        : "r"(a[0]), "r"(a[1]), "r"(a[2]), "r"(a[3]), "r"(b0), "r"(b1));
}
__device__ __forceinline__ void cp16(uint32_t saddr, const void* gptr) {
    asm volatile("cp.async.cg.shared.global [%0], [%1], 16;" :: "r"(saddr), "l"(gptr));
}
__device__ __forceinline__ void cp_commit() { asm volatile("cp.async.commit_group;"); }
template<int N> __device__ __forceinline__ void cp_wait() {
    asm volatile("cp.async.wait_group %0;" :: "n"(N));
}

// ---------------- zero accumulators ----------------------------------------
__global__ void zero_kernel() {
    int i = threadIdx.x;
    float* pM = &g_M[0][0][0][0];
    for (int e = i; e < 2 * BB * HH * 36; e += 256) pM[e] = 0.f;
    float* pk = &g_klsum[0][0][0];
    float* pd = &g_dq2[0][0][0];
    float* pm = &g_dm1[0][0][0];
    for (int e = i; e < 2 * BB * HH; e += 256) { pk[e] = 0.f; pd[e] = 0.f; pm[e] = 0.f; }
}

// ---------------- clustering (unchanged from passing R2) -------------------
__global__ __launch_bounds__(256) void clustering_kernel(
    const float* __restrict__ qin, const float* __restrict__ kin,
    const float* __restrict__ mu, const float* __restrict__ logvar,
    const float* __restrict__ logprior)
{
    __shared__ float mu_s[NC][DK];
    __shared__ float iv_s[NC][DK];
    __shared__ float lvs_s[NC], ratio_s[NC], logp_s[NC], prior_s[NC];

    int bx = blockIdx.x;
    int s = bx >> 5;
    int rem = bx & 31;
    int b = rem >> 3;
    int h = rem & 7;
    int tid = threadIdx.x;
    int l = blockIdx.y * 256 + tid;

    for (int idx = tid; idx < NC * DK; idx += 256) {
        int c = idx >> 6, d = idx & 63;
        float lv = logvar[(h * NC + c) * DK + d];
        mu_s[c][d] = mu[(h * NC + c) * DK + d];
        iv_s[c][d] = expf(-lv);
    }
    __syncthreads();
    if (tid < NC) {
        float ls = 0.f, rs = 0.f;
        const float avar = expf(LOG_AV);
        for (int d = 0; d < DK; d++) {
            ls += logvar[(h * NC + tid) * DK + d];
            rs += iv_s[tid][d];
        }
        lvs_s[tid] = ls;
        ratio_s[tid] = avar * rs;
    }
    if (tid == 0) {
        float mx = -1e30f;
        for (int c = 0; c < NC; c++) mx = fmaxf(mx, logprior[h * NC + c]);
        float ss = 0.f;
        for (int c = 0; c < NC; c++) ss += expf(logprior[h * NC + c] - mx);
        float lse = mx + logf(ss);
        for (int c = 0; c < NC; c++) {
            logp_s[c] = logprior[h * NC + c] - lse;
            prior_s[c] = expf(logp_s[c]);
        }
    }
    __syncthreads();

    const float* src = (s == 0) ? qin : kin;
    const float* xr = src + ((size_t)b * LL + l) * DMODEL + h * DK;

    float x[DK];
#pragma unroll
    for (int d = 0; d < DK; d++) x[d] = xr[d];

    float mse[NC], logit[NC];
#pragma unroll
    for (int c = 0; c < NC; c++) {
        float a = 0.f;
#pragma unroll
        for (int d = 0; d < DK; d++) {
            float t = x[d] - mu_s[c][d];
            a = fmaf(t * t, iv_s[c][d], a);
        }
        mse[c] = a;
        logit[c] = -0.5f * a - 0.5f * lvs_s[c] + logp_s[c];
    }
    float m = logit[0];
#pragma unroll
    for (int c = 1; c < NC; c++) m = fmaxf(m, logit[c]);
    float p[NC];
    float Zl = 0.f;
#pragma unroll
    for (int c = 0; c < NC; c++) { p[c] = expf(logit[c] - m); Zl += p[c]; }
    float lz = logf(Zl);
    float inv = 1.f / Zl;

    float t1 = 0.f;
#pragma unroll
    for (int c = 0; c < NC; c++)
        t1 += prior_s[c] * (logp_s[c] - (logit[c] - m - lz));
#pragma unroll
    for (int c = 0; c < NC; c++) p[c] *= inv;
    float t2 = 0.f;
#pragma unroll
    for (int c = 0; c < NC; c++)
        t2 += p[c] * (mse[c] + ratio_s[c] + lvs_s[c]);
    float klloc = t1 + 0.5f * t2;

    float dq = 0.f;
#pragma unroll
    for (int c = 0; c < NC; c++) dq = fmaf(p[c], p[c], dq);
    float dq2loc = dq * dq;
    float dm1loc = (dq - 1.f) * (dq - 1.f);

    float Ml[36];
    {
        int e = 0;
#pragma unroll
        for (int c = 0; c < NC; c++)
#pragma unroll
            for (int c2 = c; c2 < NC; c2++) Ml[e++] = p[c] * p[c2];
    }
#pragma unroll
    for (int c = 0; c < NC; c++) g_probs[s][b][h][l][c] = p[c];

#pragma unroll
    for (int e = 0; e < 36; e++) {
        float v = Ml[e];
        v += __shfl_xor_sync(0xffffffffu, v, 16);
        v += __shfl_xor_sync(0xffffffffu, v, 8);
        v += __shfl_xor_sync(0xffffffffu, v, 4);
        v += __shfl_xor_sync(0xffffffffu, v, 2);
        v += __shfl_xor_sync(0xffffffffu, v, 1);
        if ((tid & 31) == 0) atomicAdd(&g_M[s][b][h][e], v);
    }
    float v3[3] = { klloc, dq2loc, dm1loc };
    float* dsts[3] = { &g_klsum[s][b][h], &g_dq2[s][b][h], &g_dm1[s][b][h] };
#pragma unroll
    for (int e = 0; e < 3; e++) {
        float v = v3[e];
        v += __shfl_xor_sync(0xffffffffu, v, 16);
        v += __shfl_xor_sync(0xffffffffu, v, 8);
        v += __shfl_xor_sync(0xffffffffu, v, 4);
        v += __shfl_xor_sync(0xffffffffu, v, 2);
        v += __shfl_xor_sync(0xffffffffu, v, 1);
        if ((tid & 31) == 0) atomicAdd(dsts[e], v);
    }
}

// ---------------- cp.async 3-stage tf32 GEMM --------------------------------
// CTA 128x128, 8 warps (4m x 2n), warp tile 32x64, k-chunk 16, 3 stages.
// mode 0/1/2 -> g_q/g_k/g_v as tf32 bits; 3 -> fp32 flat out.
#define GSTR 20
#define GSTAGE 20480            // (128*20 A + 128*20 B) * 4B
struct GArgs {
    const float* A[3];
    const float* W[3];
    const float* Bi[3];
    float sc[3];
    int md[3];
    float* outp;
};

__global__ __launch_bounds__(256, 2) void gemm_tf32(GArgs ga)
{
    extern __shared__ uint8_t sm[];
    int z = blockIdx.z;
    const float* Ap = ga.A[z];
    if (!Ap) Ap = &g_ctx[0][0][0];
    const float* Wp = ga.W[z];
    const float* bias = ga.Bi[z];
    float scale = ga.sc[z];
    int out_mode = ga.md[z];

    int tid = threadIdx.x;
    int lane = tid & 31, wid = tid >> 5;
    int g = lane >> 2, q = lane & 3;
    int wm = wid & 3, wn = wid >> 2;
    int m0 = blockIdx.y * 128, n0 = blockIdx.x * 128;

    auto issue = [&](int kc, int stg) {
        uint32_t base = (uint32_t)__cvta_generic_to_shared(sm + stg * GSTAGE);
#pragma unroll
        for (int i = 0; i < 2; i++) {
            int cid = tid + 256 * i;
            int row = cid >> 2, c = cid & 3;
            cp16(base + (row * GSTR + c * 4) * 4,
                 Ap + (size_t)(m0 + row) * 512 + kc * 16 + c * 4);
            cp16(base + 10240 + (row * GSTR + c * 4) * 4,
                 Wp + (size_t)(n0 + row) * 512 + kc * 16 + c * 4);
        }
    };

    float acc[2][8][4];
#pragma unroll
    for (int mt = 0; mt < 2; mt++)
#pragma unroll
        for (int nt = 0; nt < 8; nt++)
#pragma unroll
            for (int s = 0; s < 4; s++) acc[mt][nt][s] = 0.f;

    issue(0, 0); cp_commit();
    issue(1, 1); cp_commit();

    for (int kc = 0; kc < 32; kc++) {
        if (kc < 31) cp_wait<1>(); else cp_wait<0>();
        __syncthreads();
        if (kc + 2 < 32) { issue(kc + 2, (kc + 2) % 3); cp_commit(); }

        const float* As = (const float*)(sm + (kc % 3) * GSTAGE);
        const float* Bs = As + 2560;
#pragma unroll
        for (int ks = 0; ks < 2; ks++) {
            uint32_t a[2][4];
#pragma unroll
            for (int mt = 0; mt < 2; mt++) {
                int mr = wm * 32 + mt * 16;
                a[mt][0] = f2tf(As[(mr + g) * GSTR + ks * 8 + q]);
                a[mt][1] = f2tf(As[(mr + g + 8) * GSTR + ks * 8 + q]);
                a[mt][2] = f2tf(As[(mr + g) * GSTR + ks * 8 + q + 4]);
                a[mt][3] = f2tf(As[(mr + g + 8) * GSTR + ks * 8 + q + 4]);
            }
#pragma unroll
            for (int nt = 0; nt < 8; nt++) {
                uint32_t b0 = f2tf(Bs[(wn * 64 + nt * 8 + g) * GSTR + ks * 8 + q]);
                uint32_t b1 = f2tf(Bs[(wn * 64 + nt * 8 + g) * GSTR + ks * 8 + q + 4]);
                mma8(acc[0][nt], a[0], b0, b1);
                mma8(acc[1][nt], a[1], b0, b1);
            }
        }
    }

#pragma unroll
    for (int mt = 0; mt < 2; mt++) {
#pragma unroll
        for (int nt = 0; nt < 8; nt++) {
#pragma unroll
            for (int s = 0; s < 4; s++) {
                int row = m0 + wm * 32 + mt * 16 + g + ((s >= 2) ? 8 : 0);
                int col = n0 + wn * 64 + nt * 8 + 2 * q + (s & 1);
                float v = (acc[mt][nt][s] + bias[col]) * scale;
                if (out_mode == 3) {
                    ga.outp[(size_t)row * 512 + col] = v;
                } else {
                    int bb = row >> 10, l = row & 1023;
                    int hh = col >> 6, dd = col & 63;
                    uint32_t* dst = (out_mode == 0) ? &g_q[0][0][0][0]
                                  : (out_mode == 1) ? &g_k[0][0][0][0]
                                                    : &g_v[0][0][0][0];
                    dst[(((size_t)(bb * HH + hh)) * LL + l) * DK + dd] = f2tf(v);
                }
            }
        }
    }
}

// ---------------- fused flash attention, cp.async double-buffered -----------
#define KSTR 68
#define VSTR 72
#define ASK  17408              // 64*68*4
#define ASV  18432              // 64*72*4
#define ASP  2048               // pks
#define ASTAGE 38144            // ASK+ASV+ASP+256

__global__ __launch_bounds__(128) void attn_tf32(const float* __restrict__ pm)
{
    extern __shared__ uint8_t sm[];

    int bh = blockIdx.x;
    int b = bh >> 3, h = bh & 7;
    int q0 = blockIdx.y * 64;
    int tid = threadIdx.x;
    int lane = tid & 31, w = tid >> 5;
    int g = lane >> 2, q = lane & 3;
    int r0 = q0 + w * 16 + g;
    int r1 = r0 + 8;

    auto issue = [&](int t, int stg) {
        int k0 = t * 64;
        uint32_t base = (uint32_t)__cvta_generic_to_shared(sm + stg * ASTAGE);
#pragma unroll
        for (int i = 0; i < 8; i++) {
            int cid = tid + 128 * i;
            int row = cid >> 4, c = cid & 15;
            cp16(base + (row * KSTR + c * 4) * 4, &g_k[b][h][k0 + row][c * 4]);
            cp16(base + ASK + (row * VSTR + c * 4) * 4, &g_v[b][h][k0 + row][c * 4]);
        }
        cp16(base + ASK + ASV + tid * 16, &g_probs[1][b][h][k0][0] + tid * 4);
        if (tid < 16)
            cp16(base + ASK + ASV + ASP + tid * 16, pm + (size_t)b * LL + k0 + tid * 4);
    };

    // Q fragments (already tf32 bits) + pq rows
    uint32_t qa[8][4];
#pragma unroll
    for (int ks = 0; ks < 8; ks++) {
        qa[ks][0] = g_q[b][h][r0][ks * 8 + q];
        qa[ks][1] = g_q[b][h][r1][ks * 8 + q];
        qa[ks][2] = g_q[b][h][r0][ks * 8 + q + 4];
        qa[ks][3] = g_q[b][h][r1][ks * 8 + q + 4];
    }
    float pq0[8], pq1[8];
#pragma unroll
    for (int c = 0; c < NC; c++) {
        pq0[c] = g_probs[0][b][h][r0][c];
        pq1[c] = g_probs[0][b][h][r1][c];
    }

    float accO[8][4];
#pragma unroll
    for (int nt = 0; nt < 8; nt++)
#pragma unroll
        for (int s = 0; s < 4; s++) accO[nt][s] = 0.f;
    float mrow0 = -1e30f, mrow1 = -1e30f, Z0 = 0.f, Z1 = 0.f;

    issue(0, 0); cp_commit();

    for (int t = 0; t < 16; t++) {
        cp_wait<0>();
        __syncthreads();
        if (t < 15) { issue(t + 1, (t + 1) & 1); cp_commit(); }

        const uint32_t* Ks = (const uint32_t*)(sm + (t & 1) * ASTAGE);
        const uint32_t* Vs = Ks + ASK / 4;
        const float* pks = (const float*)(sm + (t & 1) * ASTAGE + ASK + ASV);
        const float* padk = pks + 512;

        // bias = -10000*cmask (exact fp32), u = bias copy
        float accS[8][4], u[8][4];
#pragma unroll
        for (int nt = 0; nt < 8; nt++) {
#pragma unroll
            for (int j = 0; j < 2; j++) {
                int c = nt * 8 + 2 * q + j;
                float4 pA = *(const float4*)&pks[c * 8];
                float4 pB = *(const float4*)&pks[c * 8 + 4];
                float s0 = pq0[0] * pA.x + pq0[1] * pA.y + pq0[2] * pA.z + pq0[3] * pA.w
                         + pq0[4] * pB.x + pq0[5] * pB.y + pq0[6] * pB.z + pq0[7] * pB.w;
                float s1 = pq1[0] * pA.x + pq1[1] * pA.y + pq1[2] * pA.z + pq1[3] * pA.w
                         + pq1[4] * pB.x + pq1[5] * pB.y + pq1[6] * pB.z + pq1[7] * pB.w;
                float pd = padk[c];
                float cm0 = fminf(fmaxf(1.f - s0 + pd, 0.f), 1.f);
                float cm1 = fminf(fmaxf(1.f - s1 + pd, 0.f), 1.f);
                accS[nt][j]     = -10000.f * cm0; u[nt][j]     = accS[nt][j];
                accS[nt][2 + j] = -10000.f * cm1; u[nt][2 + j] = accS[nt][2 + j];
            }
        }

        // S += Q * K^T
#pragma unroll
        for (int ks = 0; ks < 8; ks++) {
#pragma unroll
            for (int nt = 0; nt < 8; nt++) {
                uint32_t b0 = Ks[(nt * 8 + g) * KSTR + ks * 8 + q];
                uint32_t b1 = Ks[(nt * 8 + g) * KSTR + ks * 8 + q + 4];
                mma8(accS[nt], qa[ks], b0, b1);
            }
        }

        // online softmax
        float t0 = accS[0][0], t1v = accS[0][2];
#pragma unroll
        for (int nt = 0; nt < 8; nt++) {
            t0 = fmaxf(t0, fmaxf(accS[nt][0], accS[nt][1]));
            t1v = fmaxf(t1v, fmaxf(accS[nt][2], accS[nt][3]));
        }
        t0 = fmaxf(t0, __shfl_xor_sync(0xffffffffu, t0, 1));
        t0 = fmaxf(t0, __shfl_xor_sync(0xffffffffu, t0, 2));
        t1v = fmaxf(t1v, __shfl_xor_sync(0xffffffffu, t1v, 1));
        t1v = fmaxf(t1v, __shfl_xor_sync(0xffffffffu, t1v, 2));
        float mn0 = fmaxf(mrow0, t0), mn1 = fmaxf(mrow1, t1v);
        float corr0 = __expf(mrow0 - mn0), corr1 = __expf(mrow1 - mn1);
        mrow0 = mn0; mrow1 = mn1;
        Z0 *= corr0; Z1 *= corr1;
#pragma unroll
        for (int nt = 0; nt < 8; nt++) {
            accO[nt][0] *= corr0; accO[nt][1] *= corr0;
            accO[nt][2] *= corr1; accO[nt][3] *= corr1;
        }
        float z0 = 0.f, z1 = 0.f;
#pragma unroll
        for (int nt = 0; nt < 8; nt++) {
            float e0 = __expf(accS[nt][0] - mn0);
            float e1 = __expf(accS[nt][1] - mn0);
            float e2 = __expf(accS[nt][2] - mn1);
            float e3 = __expf(accS[nt][3] - mn1);
            z0 += e0 + e1; z1 += e2 + e3;
            accS[nt][0] = e0 * (1.f + u[nt][0] * 1e-4f);
            accS[nt][1] = e1 * (1.f + u[nt][1] * 1e-4f);
            accS[nt][2] = e2 * (1.f + u[nt][2] * 1e-4f);
            accS[nt][3] = e3 * (1.f + u[nt][3] * 1e-4f);
        }
        Z0 += z0; Z1 += z1;

        // O += P * V : permute C-frag -> A-frag via quad shuffles
        int srcA = (lane & ~3) | (q >> 1);
        int srcB = srcA + 2;
        bool odd = (q & 1);
#pragma unroll
        for (int kg = 0; kg < 8; kg++) {
            float x0 = __shfl_sync(0xffffffffu, accS[kg][0], srcA);
            float x1 = __shfl_sync(0xffffffffu, accS[kg][1], srcA);
            float x4 = __shfl_sync(0xffffffffu, accS[kg][0], srcB);
            float x5 = __shfl_sync(0xffffffffu, accS[kg][1], srcB);
            float y0 = __shfl_sync(0xffffffffu, accS[kg][2], srcA);
            float y1 = __shfl_sync(0xffffffffu, accS[kg][3], srcA);
            float y4 = __shfl_sync(0xffffffffu, accS[kg][2], srcB);
            float y5 = __shfl_sync(0xffffffffu, accS[kg][3], srcB);
            uint32_t a[4];
            a[0] = f2tf(odd ? x1 : x0);
            a[1] = f2tf(odd ? y1 : y0);
            a[2] = f2tf(odd ? x5 : x4);
            a[3] = f2tf(odd ? y5 : y4);
#pragma unroll
            for (int nt = 0; nt < 8; nt++) {
                uint32_t b0 = Vs[(kg * 8 + q) * VSTR + nt * 8 + g];
                uint32_t b1 = Vs[(kg * 8 + q + 4) * VSTR + nt * 8 + g];
                mma8(accO[nt], a, b0, b1);
            }
        }
    }

    Z0 += __shfl_xor_sync(0xffffffffu, Z0, 1);
    Z0 += __shfl_xor_sync(0xffffffffu, Z0, 2);
    Z1 += __shfl_xor_sync(0xffffffffu, Z1, 1);
    Z1 += __shfl_xor_sync(0xffffffffu, Z1, 2);
    float iz0 = 1.f / Z0, iz1 = 1.f / Z1;
#pragma unroll
    for (int nt = 0; nt < 8; nt++) {
        float2 o0 = make_float2(accO[nt][0] * iz0, accO[nt][1] * iz0);
        float2 o1 = make_float2(accO[nt][2] * iz1, accO[nt][3] * iz1);
        *(float2*)&g_ctx[b][r0][h * DK + nt * 8 + 2 * q] = o0;
        *(float2*)&g_ctx[b][r1][h * DK + nt * 8 + 2 * q] = o1;
    }
}

// ---------------- finalize ---------------------------------------------------
__global__ void finalize_kernel(float* __restrict__ out, int out_size)
{
    int b = threadIdx.x;
    if (b >= BB) return;
    float kl = 0.f;
    for (int s = 0; s < 2; s++)
        for (int h = 0; h < HH; h++) kl += g_klsum[s][b][h];
    const float c3 = -0.5f * (1.0f + LOG_AV) * (float)DK;
    float kl_total = kl / (float)(HH * LL) + 2.f * c3;

    float dv = 0.f;
    for (int s = 0; s < 2; s++)
        for (int h = 0; h < HH; h++) {
            float frob = 0.f;
            int e = 0;
            for (int c = 0; c < NC; c++)
                for (int c2 = c; c2 < NC; c2++) {
                    float mv = g_M[s][b][h][e++];
                    frob += (c2 == c) ? mv * mv : 2.f * mv * mv;
                }
            dv += 0.75f * (frob - g_dq2[s][b][h]) + 1.25f * g_dm1[s][b][h];
        }
    dv /= (float)HH * (float)LL * (float)LL;

    long base = (long)BB * LL * DMODEL;
    if (out_size >= base + 2 * BB) {
        out[base + b] = kl_total;
        out[base + BB + b] = dv;
    }
}

// ---------------- launch -----------------------------------------------------
extern "C" void kernel_launch(void* const* d_in, const int* in_sizes, int n_in,
                              void* d_out, int out_size)
{
    const float* query  = (const float*)d_in[0];
    const float* key    = (const float*)d_in[1];
    const float* value  = (const float*)d_in[2];
    const float* pmask  = (const float*)d_in[3];
    const float* Wq = (const float*)d_in[4];
    const float* bq = (const float*)d_in[5];
    const float* Wk = (const float*)d_in[6];
    const float* bk = (const float*)d_in[7];
    const float* Wv = (const float*)d_in[8];
    const float* bv = (const float*)d_in[9];
    const float* Wo = (const float*)d_in[10];
    const float* bo = (const float*)d_in[11];
    const float* tok_mu = (const float*)d_in[12];
    const float* tok_lv = (const float*)d_in[13];
    const float* tok_lp = (const float*)d_in[14];
    float* outp = (float*)d_out;

    cudaFuncSetAttribute(gemm_tf32, cudaFuncAttributeMaxDynamicSharedMemorySize, 3 * GSTAGE);
    cudaFuncSetAttribute(attn_tf32, cudaFuncAttributeMaxDynamicSharedMemorySize, 2 * ASTAGE);

    zero_kernel<<<1, 256>>>();
    clustering_kernel<<<dim3(2 * BB * HH, 4), 256>>>(query, key, tok_mu, tok_lv, tok_lp);

    GArgs qkv;
    qkv.A[0] = query; qkv.A[1] = key; qkv.A[2] = value;
    qkv.W[0] = Wq;    qkv.W[1] = Wk;  qkv.W[2] = Wv;
    qkv.Bi[0] = bq;   qkv.Bi[1] = bk; qkv.Bi[2] = bv;
    qkv.sc[0] = 0.125f; qkv.sc[1] = 1.f; qkv.sc[2] = 1.f;
    qkv.md[0] = 0; qkv.md[1] = 1; qkv.md[2] = 2;
    qkv.outp = nullptr;
    gemm_tf32<<<dim3(4, 32, 3), 256, 3 * GSTAGE>>>(qkv);

    attn_tf32<<<dim3(BB * HH, LL / 64), 128, 2 * ASTAGE>>>(pmask);

    GArgs og;
    og.A[0] = nullptr; og.A[1] = nullptr; og.A[2] = nullptr;
    og.W[0] = Wo; og.W[1] = Wo; og.W[2] = Wo;
    og.Bi[0] = bo; og.Bi[1] = bo; og.Bi[2] = bo;
    og.sc[0] = 1.f; og.sc[1] = 1.f; og.sc[2] = 1.f;
    og.md[0] = 3; og.md[1] = 3; og.md[2] = 3;
    og.outp = outp;
    gemm_tf32<<<dim3(4, 32, 1), 256, 3 * GSTAGE>>>(og);

    finalize_kernel<<<1, 32>>>(outp, out_size);
}

// round 4
// speedup vs baseline: 4.2388x; 1.0364x over previous
#include <cuda_runtime.h>
#include <math.h>
#include <stdint.h>

#define BB 4
#define LL 1024
#define DMODEL 512
#define HH 8
#define NC 8
#define DK 64
#define LOG_AV (-4.605170185988091f)   // log(0.01)

// ---------------- scratch (device globals: no allocation allowed) ----------
__device__ __align__(256) float g_probs[2][BB][HH][LL][NC]; // 0=q,1=k
// mma-fragment-packed tf32 bits:
// Q (A-frag):  [l/16][d/8][lane]{a0,a1,a2,a3}
// K (B-frag):  [l/8][d/16][lane]{b0e,b1e,b0o,b1o}   (ks pairs packed)
// V (B-frag):  [k/16][d/8][lane]{b0e,b1e,b0o,b1o}   (kg pairs packed)
__device__ __align__(256) uint4 g_qf[BB][HH][64][8][32];
__device__ __align__(256) uint4 g_kf[BB][HH][128][4][32];
__device__ __align__(256) uint4 g_vf[BB][HH][64][8][32];
__device__ __align__(256) float g_ctx[BB][LL][DMODEL];
__device__ float g_M[2][BB][HH][36];
__device__ float g_klsum[2][BB][HH];
__device__ float g_dq2[2][BB][HH];
__device__ float g_dm1[2][BB][HH];

// ---------------- helpers ---------------------------------------------------
__device__ __forceinline__ uint32_t f2tf(float x) {
    uint32_t r;
    asm("cvt.rna.tf32.f32 %0, %1;" : "=r"(r) : "f"(x));
    return r;
}
__device__ __forceinline__ void mma8(float* c, const uint32_t* a, uint32_t b0, uint32_t b1) {
    asm volatile(
        "mma.sync.aligned.m16n8k8.row.col.f32.tf32.tf32.f32 "
        "{%0,%1,%2,%3}, {%4,%5,%6,%7}, {%8,%9}, {%0,%1,%2,%3};"
        : "+f"(c[0]), "+f"(c[1]), "+f"(c[2]), "+f"(c[3])
        : "r"(a[0]), "r"(a[1]), "r"(a[2]), "r"(a[3]), "r"(b0), "r"(b1));
}
__device__ __forceinline__ void cp16(uint32_t saddr, const void* gptr) {
    asm volatile("cp.async.cg.shared.global [%0], [%1], 16;" :: "r"(saddr), "l"(gptr));
}
__device__ __forceinline__ void cp_commit() { asm volatile("cp.async.commit_group;"); }
template<int N> __device__ __forceinline__ void cp_wait() {
    asm volatile("cp.async.wait_group %0;" :: "n"(N));
}

// ---------------- zero accumulators ----------------------------------------
__global__ void zero_kernel() {
    int i = threadIdx.x;
    float* pM = &g_M[0][0][0][0];
    for (int e = i; e < 2 * BB * HH * 36; e += 256) pM[e] = 0.f;
    float* pk = &g_klsum[0][0][0];
    float* pd = &g_dq2[0][0][0];
    float* pm = &g_dm1[0][0][0];
    for (int e = i; e < 2 * BB * HH; e += 256) { pk[e] = 0.f; pd[e] = 0.f; pm[e] = 0.f; }
}

// ---------------- clustering: probs + kl only -------------------------------
__global__ __launch_bounds__(256) void clustering_kernel(
    const float* __restrict__ qin, const float* __restrict__ kin,
    const float* __restrict__ mu, const float* __restrict__ logvar,
    const float* __restrict__ logprior)
{
    __shared__ float mu_s[NC][DK];
    __shared__ float iv_s[NC][DK];
    __shared__ float lvs_s[NC], ratio_s[NC], logp_s[NC], prior_s[NC];

    int bx = blockIdx.x;
    int s = bx >> 5;
    int rem = bx & 31;
    int b = rem >> 3;
    int h = rem & 7;
    int tid = threadIdx.x;
    int l = blockIdx.y * 256 + tid;

    for (int idx = tid; idx < NC * DK; idx += 256) {
        int c = idx >> 6, d = idx & 63;
        float lv = logvar[(h * NC + c) * DK + d];
        mu_s[c][d] = mu[(h * NC + c) * DK + d];
        iv_s[c][d] = expf(-lv);
    }
    __syncthreads();
    if (tid < NC) {
        float ls = 0.f, rs = 0.f;
        const float avar = expf(LOG_AV);
        for (int d = 0; d < DK; d++) {
            ls += logvar[(h * NC + tid) * DK + d];
            rs += iv_s[tid][d];
        }
        lvs_s[tid] = ls;
        ratio_s[tid] = avar * rs;
    }
    if (tid == 0) {
        float mx = -1e30f;
        for (int c = 0; c < NC; c++) mx = fmaxf(mx, logprior[h * NC + c]);
        float ss = 0.f;
        for (int c = 0; c < NC; c++) ss += expf(logprior[h * NC + c] - mx);
        float lse = mx + logf(ss);
        for (int c = 0; c < NC; c++) {
            logp_s[c] = logprior[h * NC + c] - lse;
            prior_s[c] = expf(logp_s[c]);
        }
    }
    __syncthreads();

    const float* src = (s == 0) ? qin : kin;
    const float4* xr4 = (const float4*)(src + ((size_t)b * LL + l) * DMODEL + h * DK);

    float x[DK];
#pragma unroll
    for (int dd = 0; dd < 16; dd++) {
        float4 v = xr4[dd];
        x[dd * 4] = v.x; x[dd * 4 + 1] = v.y; x[dd * 4 + 2] = v.z; x[dd * 4 + 3] = v.w;
    }

    float mse[NC], logit[NC];
#pragma unroll
    for (int c = 0; c < NC; c++) {
        float a = 0.f;
#pragma unroll
        for (int d = 0; d < DK; d++) {
            float t = x[d] - mu_s[c][d];
            a = fmaf(t * t, iv_s[c][d], a);
        }
        mse[c] = a;
        logit[c] = -0.5f * a - 0.5f * lvs_s[c] + logp_s[c];
    }
    float m = logit[0];
#pragma unroll
    for (int c = 1; c < NC; c++) m = fmaxf(m, logit[c]);
    float p[NC];
    float Zl = 0.f;
#pragma unroll
    for (int c = 0; c < NC; c++) { p[c] = expf(logit[c] - m); Zl += p[c]; }
    float lz = logf(Zl);
    float inv = 1.f / Zl;

    float t1 = 0.f;
#pragma unroll
    for (int c = 0; c < NC; c++)
        t1 += prior_s[c] * (logp_s[c] - (logit[c] - m - lz));
#pragma unroll
    for (int c = 0; c < NC; c++) p[c] *= inv;
    float t2 = 0.f;
#pragma unroll
    for (int c = 0; c < NC; c++)
        t2 += p[c] * (mse[c] + ratio_s[c] + lvs_s[c]);
    float klloc = t1 + 0.5f * t2;

#pragma unroll
    for (int c = 0; c < NC; c++) g_probs[s][b][h][l][c] = p[c];

    float v = klloc;
    v += __shfl_xor_sync(0xffffffffu, v, 16);
    v += __shfl_xor_sync(0xffffffffu, v, 8);
    v += __shfl_xor_sync(0xffffffffu, v, 4);
    v += __shfl_xor_sync(0xffffffffu, v, 2);
    v += __shfl_xor_sync(0xffffffffu, v, 1);
    if ((tid & 31) == 0) atomicAdd(&g_klsum[s][b][h], v);
}

// ---------------- stats: M = P^T P upper-tri, dq2, dm1 ----------------------
__global__ __launch_bounds__(256) void stats_kernel()
{
    int sbh = blockIdx.x;            // 0..63
    int s = sbh >> 5, b = (sbh >> 3) & 3, h = sbh & 7;
    int tid = threadIdx.x;
    float M[36];
#pragma unroll
    for (int e = 0; e < 36; e++) M[e] = 0.f;
    float dq2 = 0.f, dm1 = 0.f;

    for (int l = tid; l < LL; l += 256) {
        float4 pA = *(const float4*)&g_probs[s][b][h][l][0];
        float4 pB = *(const float4*)&g_probs[s][b][h][l][4];
        float p[8] = { pA.x, pA.y, pA.z, pA.w, pB.x, pB.y, pB.z, pB.w };
        float dq = 0.f;
#pragma unroll
        for (int c = 0; c < 8; c++) dq = fmaf(p[c], p[c], dq);
        dq2 += dq * dq;
        dm1 += (dq - 1.f) * (dq - 1.f);
        int e = 0;
#pragma unroll
        for (int c = 0; c < 8; c++)
#pragma unroll
            for (int c2 = c; c2 < 8; c2++) M[e++] = fmaf(p[c], p[c2], M[e]);
    }

#pragma unroll
    for (int e = 0; e < 36; e++) {
        float v = M[e];
        v += __shfl_xor_sync(0xffffffffu, v, 16);
        v += __shfl_xor_sync(0xffffffffu, v, 8);
        v += __shfl_xor_sync(0xffffffffu, v, 4);
        v += __shfl_xor_sync(0xffffffffu, v, 2);
        v += __shfl_xor_sync(0xffffffffu, v, 1);
        if ((tid & 31) == 0) atomicAdd(&g_M[s][b][h][e], v);
    }
    float v2[2] = { dq2, dm1 };
    float* d2[2] = { &g_dq2[s][b][h], &g_dm1[s][b][h] };
#pragma unroll
    for (int e = 0; e < 2; e++) {
        float v = v2[e];
        v += __shfl_xor_sync(0xffffffffu, v, 16);
        v += __shfl_xor_sync(0xffffffffu, v, 8);
        v += __shfl_xor_sync(0xffffffffu, v, 4);
        v += __shfl_xor_sync(0xffffffffu, v, 2);
        v += __shfl_xor_sync(0xffffffffu, v, 1);
        if ((tid & 31) == 0) atomicAdd(d2[e], v);
    }
}

// ---------------- cp.async 3-stage tf32 GEMM --------------------------------
#define GSTR 20
#define GSTAGE 20480
struct GArgs {
    const float* A[3];
    const float* W[3];
    const float* Bi[3];
    float sc[3];
    int md[3];
    float* outp;
};

__global__ __launch_bounds__(256, 2) void gemm_tf32(GArgs ga)
{
    extern __shared__ uint8_t sm[];
    int z = blockIdx.z;
    const float* Ap = ga.A[z];
    if (!Ap) Ap = &g_ctx[0][0][0];
    const float* Wp = ga.W[z];
    const float* bias = ga.Bi[z];
    float scale = ga.sc[z];
    int out_mode = ga.md[z];

    int tid = threadIdx.x;
    int lane = tid & 31, wid = tid >> 5;
    int g = lane >> 2, q = lane & 3;
    int wm = wid & 3, wn = wid >> 2;
    int m0 = blockIdx.y * 128, n0 = blockIdx.x * 128;

    auto issue = [&](int kc, int stg) {
        uint32_t base = (uint32_t)__cvta_generic_to_shared(sm + stg * GSTAGE);
#pragma unroll
        for (int i = 0; i < 2; i++) {
            int cid = tid + 256 * i;
            int row = cid >> 2, c = cid & 3;
            cp16(base + (row * GSTR + c * 4) * 4,
                 Ap + (size_t)(m0 + row) * 512 + kc * 16 + c * 4);
            cp16(base + 10240 + (row * GSTR + c * 4) * 4,
                 Wp + (size_t)(n0 + row) * 512 + kc * 16 + c * 4);
        }
    };

    float acc[2][8][4];
#pragma unroll
    for (int mt = 0; mt < 2; mt++)
#pragma unroll
        for (int nt = 0; nt < 8; nt++)
#pragma unroll
            for (int s = 0; s < 4; s++) acc[mt][nt][s] = 0.f;

    issue(0, 0); cp_commit();
    issue(1, 1); cp_commit();

    for (int kc = 0; kc < 32; kc++) {
        if (kc < 31) cp_wait<1>(); else cp_wait<0>();
        __syncthreads();
        if (kc + 2 < 32) { issue(kc + 2, (kc + 2) % 3); cp_commit(); }

        const float* As = (const float*)(sm + (kc % 3) * GSTAGE);
        const float* Bs = As + 2560;
#pragma unroll
        for (int ks = 0; ks < 2; ks++) {
            uint32_t a[2][4];
#pragma unroll
            for (int mt = 0; mt < 2; mt++) {
                int mr = wm * 32 + mt * 16;
                a[mt][0] = f2tf(As[(mr + g) * GSTR + ks * 8 + q]);
                a[mt][1] = f2tf(As[(mr + g + 8) * GSTR + ks * 8 + q]);
                a[mt][2] = f2tf(As[(mr + g) * GSTR + ks * 8 + q + 4]);
                a[mt][3] = f2tf(As[(mr + g + 8) * GSTR + ks * 8 + q + 4]);
            }
#pragma unroll
            for (int nt = 0; nt < 8; nt++) {
                uint32_t b0 = f2tf(Bs[(wn * 64 + nt * 8 + g) * GSTR + ks * 8 + q]);
                uint32_t b1 = f2tf(Bs[(wn * 64 + nt * 8 + g) * GSTR + ks * 8 + q + 4]);
                mma8(acc[0][nt], a[0], b0, b1);
                mma8(acc[1][nt], a[1], b0, b1);
            }
        }
    }

#pragma unroll
    for (int mt = 0; mt < 2; mt++) {
#pragma unroll
        for (int nt = 0; nt < 8; nt++) {
#pragma unroll
            for (int s = 0; s < 4; s++) {
                int row = m0 + wm * 32 + mt * 16 + g + ((s >= 2) ? 8 : 0);
                int col = n0 + wn * 64 + nt * 8 + 2 * q + (s & 1);
                float v = (acc[mt][nt][s] + bias[col]) * scale;
                if (out_mode == 3) {
                    ga.outp[(size_t)row * 512 + col] = v;
                } else {
                    int bb = row >> 10, l = row & 1023;
                    int hh = col >> 6, dd = col & 63;
                    uint32_t bits = f2tf(v);
                    if (out_mode == 0) {
                        int l16 = l >> 4, gg = l & 15;
                        int ks = dd >> 3, qq = dd & 7;
                        int slot = (gg >> 3) | ((qq >> 2) << 1);
                        int ln = (gg & 7) * 4 + (qq & 3);
                        ((uint32_t*)&g_qf[bb][hh][l16][ks][ln])[slot] = bits;
                    } else if (out_mode == 1) {
                        int n8 = l >> 3, gg = l & 7;
                        int ks = dd >> 3, qq = dd & 7;
                        int slot = ((ks & 1) << 1) | (qq >> 2);
                        int ln = gg * 4 + (qq & 3);
                        ((uint32_t*)&g_kf[bb][hh][n8][ks >> 1][ln])[slot] = bits;
                    } else {
                        int kg = l >> 3, kq = l & 7;
                        int nt2 = dd >> 3, gv = dd & 7;
                        int slot = ((kg & 1) << 1) | (kq >> 2);
                        int ln = gv * 4 + (kq & 3);
                        ((uint32_t*)&g_vf[bb][hh][kg >> 1][nt2][ln])[slot] = bits;
                    }
                }
            }
        }
    }
}

// ---------------- fused flash attention, packed fragments -------------------
// stage: K frag 16KB @0, V frag 16KB @16384, pk 2KB @32768, pad 256B @34816
#define ASTG 35072

__global__ __launch_bounds__(128) void attn_tf32(const float* __restrict__ pm)
{
    extern __shared__ uint8_t sm[];

    int bh = blockIdx.x;
    int b = bh >> 3, h = bh & 7;
    int tid = threadIdx.x;
    int lane = tid & 31, w = tid >> 5;
    int g = lane >> 2, q = lane & 3;
    int q0 = blockIdx.y * 64;
    int r0 = q0 + w * 16 + g;
    int r1 = r0 + 8;

    auto issue = [&](int t, int stg) {
        uint32_t base = (uint32_t)__cvta_generic_to_shared(sm + stg * ASTG);
        const uint4* kg_ = &g_kf[b][h][t * 8][0][0];
        const uint4* vg_ = &g_vf[b][h][t * 4][0][0];
#pragma unroll
        for (int i = 0; i < 8; i++) {
            int cid = tid + 128 * i;
            cp16(base + cid * 16, kg_ + cid);
            cp16(base + 16384 + cid * 16, vg_ + cid);
        }
        cp16(base + 32768 + tid * 16, (const float*)&g_probs[1][b][h][t * 64][0] + tid * 4);
        if (tid < 16)
            cp16(base + 34816 + tid * 16, pm + (size_t)b * LL + t * 64 + tid * 4);
    };

    // Q fragments (packed) + pq rows
    uint32_t qa[8][4];
    {
        int l16 = blockIdx.y * 4 + w;
#pragma unroll
        for (int ks = 0; ks < 8; ks++) {
            uint4 t0 = g_qf[b][h][l16][ks][lane];
            qa[ks][0] = t0.x; qa[ks][1] = t0.y; qa[ks][2] = t0.z; qa[ks][3] = t0.w;
        }
    }
    float pq0[8], pq1[8];
#pragma unroll
    for (int c = 0; c < NC; c++) {
        pq0[c] = g_probs[0][b][h][r0][c];
        pq1[c] = g_probs[0][b][h][r1][c];
    }

    float accO[8][4];
#pragma unroll
    for (int nt = 0; nt < 8; nt++)
#pragma unroll
        for (int s = 0; s < 4; s++) accO[nt][s] = 0.f;
    float mrow0 = -1e30f, mrow1 = -1e30f, Z0 = 0.f, Z1 = 0.f;

    issue(0, 0); cp_commit();

    for (int t = 0; t < 16; t++) {
        cp_wait<0>();
        __syncthreads();
        if (t < 15) { issue(t + 1, (t + 1) & 1); cp_commit(); }

        const uint4* Ksm = (const uint4*)(sm + (t & 1) * ASTG);
        const uint4* Vsm = (const uint4*)(sm + (t & 1) * ASTG + 16384);
        const float* pks = (const float*)(sm + (t & 1) * ASTG + 32768);
        const float* padk = (const float*)(sm + (t & 1) * ASTG + 34816);

        // bias = -10000*cmask (exact fp32)
        float accS[8][4], u[8][4];
#pragma unroll
        for (int nt = 0; nt < 8; nt++) {
#pragma unroll
            for (int j = 0; j < 2; j++) {
                int c = nt * 8 + 2 * q + j;
                float4 pA = *(const float4*)&pks[c * 8];
                float4 pB = *(const float4*)&pks[c * 8 + 4];
                float s0 = pq0[0] * pA.x + pq0[1] * pA.y + pq0[2] * pA.z + pq0[3] * pA.w
                         + pq0[4] * pB.x + pq0[5] * pB.y + pq0[6] * pB.z + pq0[7] * pB.w;
                float s1 = pq1[0] * pA.x + pq1[1] * pA.y + pq1[2] * pA.z + pq1[3] * pA.w
                         + pq1[4] * pB.x + pq1[5] * pB.y + pq1[6] * pB.z + pq1[7] * pB.w;
                float pd = padk[c];
                float cm0 = fminf(fmaxf(1.f - s0 + pd, 0.f), 1.f);
                float cm1 = fminf(fmaxf(1.f - s1 + pd, 0.f), 1.f);
                accS[nt][j]     = -10000.f * cm0; u[nt][j]     = accS[nt][j];
                accS[nt][2 + j] = -10000.f * cm1; u[nt][2 + j] = accS[nt][2 + j];
            }
        }

        // S += Q * K^T  (packed: one LDS.128 covers two k-blocks)
#pragma unroll
        for (int ks2 = 0; ks2 < 4; ks2++) {
#pragma unroll
            for (int nt = 0; nt < 8; nt++) {
                uint4 kb = Ksm[(nt * 4 + ks2) * 32 + lane];
                mma8(accS[nt], qa[2 * ks2], kb.x, kb.y);
                mma8(accS[nt], qa[2 * ks2 + 1], kb.z, kb.w);
            }
        }

        // online softmax
        float t0 = accS[0][0], t1v = accS[0][2];
#pragma unroll
        for (int nt = 0; nt < 8; nt++) {
            t0 = fmaxf(t0, fmaxf(accS[nt][0], accS[nt][1]));
            t1v = fmaxf(t1v, fmaxf(accS[nt][2], accS[nt][3]));
        }
        t0 = fmaxf(t0, __shfl_xor_sync(0xffffffffu, t0, 1));
        t0 = fmaxf(t0, __shfl_xor_sync(0xffffffffu, t0, 2));
        t1v = fmaxf(t1v, __shfl_xor_sync(0xffffffffu, t1v, 1));
        t1v = fmaxf(t1v, __shfl_xor_sync(0xffffffffu, t1v, 2));
        float mn0 = fmaxf(mrow0, t0), mn1 = fmaxf(mrow1, t1v);
        float corr0 = __expf(mrow0 - mn0), corr1 = __expf(mrow1 - mn1);
        mrow0 = mn0; mrow1 = mn1;
        Z0 *= corr0; Z1 *= corr1;
#pragma unroll
        for (int nt = 0; nt < 8; nt++) {
            accO[nt][0] *= corr0; accO[nt][1] *= corr0;
            accO[nt][2] *= corr1; accO[nt][3] *= corr1;
        }
        float z0 = 0.f, z1 = 0.f;
#pragma unroll
        for (int nt = 0; nt < 8; nt++) {
            float e0 = __expf(accS[nt][0] - mn0);
            float e1 = __expf(accS[nt][1] - mn0);
            float e2 = __expf(accS[nt][2] - mn1);
            float e3 = __expf(accS[nt][3] - mn1);
            z0 += e0 + e1; z1 += e2 + e3;
            accS[nt][0] = e0 * (1.f + u[nt][0] * 1e-4f);
            accS[nt][1] = e1 * (1.f + u[nt][1] * 1e-4f);
            accS[nt][2] = e2 * (1.f + u[nt][2] * 1e-4f);
            accS[nt][3] = e3 * (1.f + u[nt][3] * 1e-4f);
        }
        Z0 += z0; Z1 += z1;

        // O += P * V : permute C-frag -> A-frag via quad shuffles, packed V
        int srcA = (lane & ~3) | (q >> 1);
        int srcB = srcA + 2;
        bool odd = (q & 1);
#pragma unroll
        for (int kg2 = 0; kg2 < 4; kg2++) {
            uint32_t aP[2][4];
#pragma unroll
            for (int half = 0; half < 2; half++) {
                int kg = 2 * kg2 + half;
                float x0 = __shfl_sync(0xffffffffu, accS[kg][0], srcA);
                float x1 = __shfl_sync(0xffffffffu, accS[kg][1], srcA);
                float x4 = __shfl_sync(0xffffffffu, accS[kg][0], srcB);
                float x5 = __shfl_sync(0xffffffffu, accS[kg][1], srcB);
                float y0 = __shfl_sync(0xffffffffu, accS[kg][2], srcA);
                float y1 = __shfl_sync(0xffffffffu, accS[kg][3], srcA);
                float y4 = __shfl_sync(0xffffffffu, accS[kg][2], srcB);
                float y5 = __shfl_sync(0xffffffffu, accS[kg][3], srcB);
                aP[half][0] = f2tf(odd ? x1 : x0);
                aP[half][1] = f2tf(odd ? y1 : y0);
                aP[half][2] = f2tf(odd ? x5 : x4);
                aP[half][3] = f2tf(odd ? y5 : y4);
            }
#pragma unroll
            for (int nt = 0; nt < 8; nt++) {
                uint4 vb = Vsm[(kg2 * 8 + nt) * 32 + lane];
                mma8(accO[nt], aP[0], vb.x, vb.y);
                mma8(accO[nt], aP[1], vb.z, vb.w);
            }
        }
    }

    Z0 += __shfl_xor_sync(0xffffffffu, Z0, 1);
    Z0 += __shfl_xor_sync(0xffffffffu, Z0, 2);
    Z1 += __shfl_xor_sync(0xffffffffu, Z1, 1);
    Z1 += __shfl_xor_sync(0xffffffffu, Z1, 2);
    float iz0 = 1.f / Z0, iz1 = 1.f / Z1;
#pragma unroll
    for (int nt = 0; nt < 8; nt++) {
        float2 o0 = make_float2(accO[nt][0] * iz0, accO[nt][1] * iz0);
        float2 o1 = make_float2(accO[nt][2] * iz1, accO[nt][3] * iz1);
        *(float2*)&g_ctx[b][r0][h * DK + nt * 8 + 2 * q] = o0;
        *(float2*)&g_ctx[b][r1][h * DK + nt * 8 + 2 * q] = o1;
    }
}

// ---------------- finalize ---------------------------------------------------
__global__ void finalize_kernel(float* __restrict__ out, int out_size)
{
    int b = threadIdx.x;
    if (b >= BB) return;
    float kl = 0.f;
    for (int s = 0; s < 2; s++)
        for (int h = 0; h < HH; h++) kl += g_klsum[s][b][h];
    const float c3 = -0.5f * (1.0f + LOG_AV) * (float)DK;
    float kl_total = kl / (float)(HH * LL) + 2.f * c3;

    float dv = 0.f;
    for (int s = 0; s < 2; s++)
        for (int h = 0; h < HH; h++) {
            float frob = 0.f;
            int e = 0;
            for (int c = 0; c < NC; c++)
                for (int c2 = c; c2 < NC; c2++) {
                    float mv = g_M[s][b][h][e++];
                    frob += (c2 == c) ? mv * mv : 2.f * mv * mv;
                }
            dv += 0.75f * (frob - g_dq2[s][b][h]) + 1.25f * g_dm1[s][b][h];
        }
    dv /= (float)HH * (float)LL * (float)LL;

    long base = (long)BB * LL * DMODEL;
    if (out_size >= base + 2 * BB) {
        out[base + b] = kl_total;
        out[base + BB + b] = dv;
    }
}

// ---------------- launch -----------------------------------------------------
extern "C" void kernel_launch(void* const* d_in, const int* in_sizes, int n_in,
                              void* d_out, int out_size)
{
    const float* query  = (const float*)d_in[0];
    const float* key    = (const float*)d_in[1];
    const float* value  = (const float*)d_in[2];
    const float* pmask  = (const float*)d_in[3];
    const float* Wq = (const float*)d_in[4];
    const float* bq = (const float*)d_in[5];
    const float* Wk = (const float*)d_in[6];
    const float* bk = (const float*)d_in[7];
    const float* Wv = (const float*)d_in[8];
    const float* bv = (const float*)d_in[9];
    const float* Wo = (const float*)d_in[10];
    const float* bo = (const float*)d_in[11];
    const float* tok_mu = (const float*)d_in[12];
    const float* tok_lv = (const float*)d_in[13];
    const float* tok_lp = (const float*)d_in[14];
    float* outp = (float*)d_out;

    cudaFuncSetAttribute(gemm_tf32, cudaFuncAttributeMaxDynamicSharedMemorySize, 3 * GSTAGE);
    cudaFuncSetAttribute(attn_tf32, cudaFuncAttributeMaxDynamicSharedMemorySize, 2 * ASTG);

    zero_kernel<<<1, 256>>>();
    clustering_kernel<<<dim3(2 * BB * HH, 4), 256>>>(query, key, tok_mu, tok_lv, tok_lp);
    stats_kernel<<<64, 256>>>();

    GArgs qkv;
    qkv.A[0] = query; qkv.A[1] = key; qkv.A[2] = value;
    qkv.W[0] = Wq;    qkv.W[1] = Wk;  qkv.W[2] = Wv;
    qkv.Bi[0] = bq;   qkv.Bi[1] = bk; qkv.Bi[2] = bv;
    qkv.sc[0] = 0.125f; qkv.sc[1] = 1.f; qkv.sc[2] = 1.f;
    qkv.md[0] = 0; qkv.md[1] = 1; qkv.md[2] = 2;
    qkv.outp = nullptr;
    gemm_tf32<<<dim3(4, 32, 3), 256, 3 * GSTAGE>>>(qkv);

    attn_tf32<<<dim3(BB * HH, LL / 64), 128, 2 * ASTG>>>(pmask);

    GArgs og;
    og.A[0] = nullptr; og.A[1] = nullptr; og.A[2] = nullptr;
    og.W[0] = Wo; og.W[1] = Wo; og.W[2] = Wo;
    og.Bi[0] = bo; og.Bi[1] = bo; og.Bi[2] = bo;
    og.sc[0] = 1.f; og.sc[1] = 1.f; og.sc[2] = 1.f;
    og.md[0] = 3; og.md[1] = 3; og.md[2] = 3;
    og.outp = outp;
    gemm_tf32<<<dim3(4, 32, 1), 256, 3 * GSTAGE>>>(og);

    finalize_kernel<<<1, 32>>>(outp, out_size);
}

// round 5
// speedup vs baseline: 4.5905x; 1.0830x over previous
#include <cuda_runtime.h>
#include <math.h>
#include <stdint.h>

#define BB 4
#define LL 1024
#define DMODEL 512
#define HH 8
#define NC 8
#define DK 64
#define LOG_AV (-4.605170185988091f)   // log(0.01)

// ---------------- scratch (device globals: no allocation allowed) ----------
__device__ __align__(256) float g_probs[2][BB][HH][LL][NC]; // 0=q,1=k
// mma-fragment-packed tf32 bits:
// Q (A-frag):  [l/16][d/8][lane]{a0,a1,a2,a3}
// K (B-frag):  [l/8][d/16][lane]{b0e,b1e,b0o,b1o}
// V (B-frag):  [k/16][d/8][lane]{b0e,b1e,b0o,b1o}
__device__ __align__(256) uint4 g_qf[BB][HH][64][8][32];
__device__ __align__(256) uint4 g_kf[BB][HH][128][4][32];
__device__ __align__(256) uint4 g_vf[BB][HH][64][8][32];
// W (B-frag): [w][n/8][k/16][lane]{b0e,b1e,b0o,b1o}
__device__ __align__(256) uint4 g_wf[4][64][32][32];
__device__ __align__(256) float g_ctx[BB][LL][DMODEL];
__device__ float g_M[2][BB][HH][36];
__device__ float g_klsum[2][BB][HH];
__device__ float g_dq2[2][BB][HH];
__device__ float g_dm1[2][BB][HH];

// ---------------- helpers ---------------------------------------------------
__device__ __forceinline__ uint32_t f2tf(float x) {
    uint32_t r;
    asm("cvt.rna.tf32.f32 %0, %1;" : "=r"(r) : "f"(x));
    return r;
}
__device__ __forceinline__ void mma8(float* c, const uint32_t* a, uint32_t b0, uint32_t b1) {
    asm volatile(
        "mma.sync.aligned.m16n8k8.row.col.f32.tf32.tf32.f32 "
        "{%0,%1,%2,%3}, {%4,%5,%6,%7}, {%8,%9}, {%0,%1,%2,%3};"
        : "+f"(c[0]), "+f"(c[1]), "+f"(c[2]), "+f"(c[3])
        : "r"(a[0]), "r"(a[1]), "r"(a[2]), "r"(a[3]), "r"(b0), "r"(b1));
}
__device__ __forceinline__ void cp16(uint32_t saddr, const void* gptr) {
    asm volatile("cp.async.cg.shared.global [%0], [%1], 16;" :: "r"(saddr), "l"(gptr));
}
__device__ __forceinline__ void cp_commit() { asm volatile("cp.async.commit_group;"); }
template<int N> __device__ __forceinline__ void cp_wait() {
    asm volatile("cp.async.wait_group %0;" :: "n"(N));
}

// ---------------- zero accumulators ----------------------------------------
__global__ void zero_kernel() {
    int i = threadIdx.x;
    float* pM = &g_M[0][0][0][0];
    for (int e = i; e < 2 * BB * HH * 36; e += 256) pM[e] = 0.f;
    float* pk = &g_klsum[0][0][0];
    float* pd = &g_dq2[0][0][0];
    float* pm = &g_dm1[0][0][0];
    for (int e = i; e < 2 * BB * HH; e += 256) { pk[e] = 0.f; pd[e] = 0.f; pm[e] = 0.f; }
}

// ---------------- weight pack: W[n][k] -> B-frag tf32 -----------------------
struct PArgs { const float* W[4]; };
__global__ __launch_bounds__(256) void pack_w(PArgs pa) {
    int idx = blockIdx.x * 256 + threadIdx.x;    // 4*65536 total
    int w = idx >> 16;
    int rem = idx & 65535;
    int n8 = rem >> 10;
    int k16 = (rem >> 5) & 31;
    int lane = rem & 31;
    int g = lane >> 2, q = lane & 3;
    const float* src = pa.W[w] + (size_t)(n8 * 8 + g) * 512 + k16 * 16 + q;
    uint4 v;
    v.x = f2tf(src[0]);
    v.y = f2tf(src[4]);
    v.z = f2tf(src[8]);
    v.w = f2tf(src[12]);
    g_wf[w][n8][k16][lane] = v;
}

// ---------------- clustering: probs + kl only -------------------------------
__global__ __launch_bounds__(256) void clustering_kernel(
    const float* __restrict__ qin, const float* __restrict__ kin,
    const float* __restrict__ mu, const float* __restrict__ logvar,
    const float* __restrict__ logprior)
{
    __shared__ float mu_s[NC][DK];
    __shared__ float iv_s[NC][DK];
    __shared__ float lvs_s[NC], ratio_s[NC], logp_s[NC], prior_s[NC];

    int bx = blockIdx.x;
    int s = bx >> 5;
    int rem = bx & 31;
    int b = rem >> 3;
    int h = rem & 7;
    int tid = threadIdx.x;
    int l = blockIdx.y * 256 + tid;

    for (int idx = tid; idx < NC * DK; idx += 256) {
        int c = idx >> 6, d = idx & 63;
        float lv = logvar[(h * NC + c) * DK + d];
        mu_s[c][d] = mu[(h * NC + c) * DK + d];
        iv_s[c][d] = expf(-lv);
    }
    __syncthreads();
    if (tid < NC) {
        float ls = 0.f, rs = 0.f;
        const float avar = expf(LOG_AV);
        for (int d = 0; d < DK; d++) {
            ls += logvar[(h * NC + tid) * DK + d];
            rs += iv_s[tid][d];
        }
        lvs_s[tid] = ls;
        ratio_s[tid] = avar * rs;
    }
    if (tid == 0) {
        float mx = -1e30f;
        for (int c = 0; c < NC; c++) mx = fmaxf(mx, logprior[h * NC + c]);
        float ss = 0.f;
        for (int c = 0; c < NC; c++) ss += expf(logprior[h * NC + c] - mx);
        float lse = mx + logf(ss);
        for (int c = 0; c < NC; c++) {
            logp_s[c] = logprior[h * NC + c] - lse;
            prior_s[c] = expf(logp_s[c]);
        }
    }
    __syncthreads();

    const float* src = (s == 0) ? qin : kin;
    const float4* xr4 = (const float4*)(src + ((size_t)b * LL + l) * DMODEL + h * DK);

    float x[DK];
#pragma unroll
    for (int dd = 0; dd < 16; dd++) {
        float4 v = xr4[dd];
        x[dd * 4] = v.x; x[dd * 4 + 1] = v.y; x[dd * 4 + 2] = v.z; x[dd * 4 + 3] = v.w;
    }

    float mse[NC], logit[NC];
#pragma unroll
    for (int c = 0; c < NC; c++) {
        float a = 0.f;
#pragma unroll
        for (int d = 0; d < DK; d++) {
            float t = x[d] - mu_s[c][d];
            a = fmaf(t * t, iv_s[c][d], a);
        }
        mse[c] = a;
        logit[c] = -0.5f * a - 0.5f * lvs_s[c] + logp_s[c];
    }
    float m = logit[0];
#pragma unroll
    for (int c = 1; c < NC; c++) m = fmaxf(m, logit[c]);
    float p[NC];
    float Zl = 0.f;
#pragma unroll
    for (int c = 0; c < NC; c++) { p[c] = expf(logit[c] - m); Zl += p[c]; }
    float lz = logf(Zl);
    float inv = 1.f / Zl;

    float t1 = 0.f;
#pragma unroll
    for (int c = 0; c < NC; c++)
        t1 += prior_s[c] * (logp_s[c] - (logit[c] - m - lz));
#pragma unroll
    for (int c = 0; c < NC; c++) p[c] *= inv;
    float t2 = 0.f;
#pragma unroll
    for (int c = 0; c < NC; c++)
        t2 += p[c] * (mse[c] + ratio_s[c] + lvs_s[c]);
    float klloc = t1 + 0.5f * t2;

#pragma unroll
    for (int c = 0; c < NC; c++) g_probs[s][b][h][l][c] = p[c];

    float v = klloc;
    v += __shfl_xor_sync(0xffffffffu, v, 16);
    v += __shfl_xor_sync(0xffffffffu, v, 8);
    v += __shfl_xor_sync(0xffffffffu, v, 4);
    v += __shfl_xor_sync(0xffffffffu, v, 2);
    v += __shfl_xor_sync(0xffffffffu, v, 1);
    if ((tid & 31) == 0) atomicAdd(&g_klsum[s][b][h], v);
}

// ---------------- stats: M = P^T P upper-tri, dq2, dm1 ----------------------
__global__ __launch_bounds__(256) void stats_kernel()
{
    int sbh = blockIdx.x;
    int s = sbh >> 5, b = (sbh >> 3) & 3, h = sbh & 7;
    int tid = threadIdx.x;
    float M[36];
#pragma unroll
    for (int e = 0; e < 36; e++) M[e] = 0.f;
    float dq2 = 0.f, dm1 = 0.f;

    for (int l = tid; l < LL; l += 256) {
        float4 pA = *(const float4*)&g_probs[s][b][h][l][0];
        float4 pB = *(const float4*)&g_probs[s][b][h][l][4];
        float p[8] = { pA.x, pA.y, pA.z, pA.w, pB.x, pB.y, pB.z, pB.w };
        float dq = 0.f;
#pragma unroll
        for (int c = 0; c < 8; c++) dq = fmaf(p[c], p[c], dq);
        dq2 += dq * dq;
        dm1 += (dq - 1.f) * (dq - 1.f);
        int e = 0;
#pragma unroll
        for (int c = 0; c < 8; c++)
#pragma unroll
            for (int c2 = c; c2 < 8; c2++) M[e++] = fmaf(p[c], p[c2], M[e]);
    }

#pragma unroll
    for (int e = 0; e < 36; e++) {
        float v = M[e];
        v += __shfl_xor_sync(0xffffffffu, v, 16);
        v += __shfl_xor_sync(0xffffffffu, v, 8);
        v += __shfl_xor_sync(0xffffffffu, v, 4);
        v += __shfl_xor_sync(0xffffffffu, v, 2);
        v += __shfl_xor_sync(0xffffffffu, v, 1);
        if ((tid & 31) == 0) atomicAdd(&g_M[s][b][h][e], v);
    }
    float v2[2] = { dq2, dm1 };
    float* d2[2] = { &g_dq2[s][b][h], &g_dm1[s][b][h] };
#pragma unroll
    for (int e = 0; e < 2; e++) {
        float v = v2[e];
        v += __shfl_xor_sync(0xffffffffu, v, 16);
        v += __shfl_xor_sync(0xffffffffu, v, 8);
        v += __shfl_xor_sync(0xffffffffu, v, 4);
        v += __shfl_xor_sync(0xffffffffu, v, 2);
        v += __shfl_xor_sync(0xffffffffu, v, 1);
        if ((tid & 31) == 0) atomicAdd(d2[e], v);
    }
}

// ---------------- cp.async 3-stage tf32 GEMM, packed-W ----------------------
// CTA 128x128, 8 warps (4m x 2n), warp tile 32x64, k-chunk 16.
// stage: A 128x16 fp32 (stride 20) 10240B @0, B 16 n8-blk uint4 8192B @10240
#define GSTR 20
#define GSTAGE 18432
struct GArgs {
    const float* A[3];
    const float* Bi[3];
    float sc[3];
    int md[3];
    int ws[3];
    float* outp;
};

__global__ __launch_bounds__(256, 2) void gemm_tf32(GArgs ga)
{
    extern __shared__ uint8_t sm[];
    int z = blockIdx.z;
    const float* Ap = ga.A[z];
    if (!Ap) Ap = &g_ctx[0][0][0];
    const float* bias = ga.Bi[z];
    float scale = ga.sc[z];
    int out_mode = ga.md[z];
    int wsel = ga.ws[z];

    int tid = threadIdx.x;
    int lane = tid & 31, wid = tid >> 5;
    int g = lane >> 2, q = lane & 3;
    int wm = wid & 3, wn = wid >> 2;
    int m0 = blockIdx.y * 128, n0 = blockIdx.x * 128;
    int n8base = n0 >> 3;

    auto issue = [&](int kc, int stg) {
        uint32_t base = (uint32_t)__cvta_generic_to_shared(sm + stg * GSTAGE);
#pragma unroll
        for (int i = 0; i < 2; i++) {
            int cid = tid + 256 * i;
            int row = cid >> 2, c = cid & 3;
            cp16(base + (row * GSTR + c * 4) * 4,
                 Ap + (size_t)(m0 + row) * 512 + kc * 16 + c * 4);
            int n8b = cid >> 5, ln = cid & 31;
            cp16(base + 10240 + cid * 16, &g_wf[wsel][n8base + n8b][kc][ln]);
        }
    };

    float acc[2][8][4];
#pragma unroll
    for (int mt = 0; mt < 2; mt++)
#pragma unroll
        for (int nt = 0; nt < 8; nt++)
#pragma unroll
            for (int s = 0; s < 4; s++) acc[mt][nt][s] = 0.f;

    issue(0, 0); cp_commit();
    issue(1, 1); cp_commit();

    for (int kc = 0; kc < 32; kc++) {
        if (kc < 31) cp_wait<1>(); else cp_wait<0>();
        __syncthreads();
        if (kc + 2 < 32) { issue(kc + 2, (kc + 2) % 3); cp_commit(); }

        const float* As = (const float*)(sm + (kc % 3) * GSTAGE);
        const uint4* Bsm = (const uint4*)(sm + (kc % 3) * GSTAGE + 10240);

        uint4 bfr[8];
#pragma unroll
        for (int nt = 0; nt < 8; nt++)
            bfr[nt] = Bsm[(wn * 8 + nt) * 32 + lane];

#pragma unroll
        for (int ks = 0; ks < 2; ks++) {
            uint32_t a[2][4];
#pragma unroll
            for (int mt = 0; mt < 2; mt++) {
                int mr = wm * 32 + mt * 16;
                a[mt][0] = f2tf(As[(mr + g) * GSTR + ks * 8 + q]);
                a[mt][1] = f2tf(As[(mr + g + 8) * GSTR + ks * 8 + q]);
                a[mt][2] = f2tf(As[(mr + g) * GSTR + ks * 8 + q + 4]);
                a[mt][3] = f2tf(As[(mr + g + 8) * GSTR + ks * 8 + q + 4]);
            }
#pragma unroll
            for (int nt = 0; nt < 8; nt++) {
                uint32_t b0 = ks ? bfr[nt].z : bfr[nt].x;
                uint32_t b1 = ks ? bfr[nt].w : bfr[nt].y;
                mma8(acc[0][nt], a[0], b0, b1);
                mma8(acc[1][nt], a[1], b0, b1);
            }
        }
    }

    // ---------- staged epilogue: smem transpose -> coalesced STG.128 -------
    __syncthreads();
    float* S = (float*)sm + wid * 1088;      // 16 x 68 floats per warp
    int C0 = n0 + wn * 64;
    int hh = C0 >> 6;

#pragma unroll
    for (int mt = 0; mt < 2; mt++) {
        if (mt) __syncwarp();
#pragma unroll
        for (int nt = 0; nt < 8; nt++)
#pragma unroll
            for (int s = 0; s < 4; s++) {
                int r = g + ((s >= 2) ? 8 : 0);
                int ct = nt * 8 + 2 * q + (s & 1);
                S[r * 68 + ct] = (acc[mt][nt][s] + bias[C0 + ct]) * scale;
            }
        __syncwarp();

        int R0 = m0 + wm * 32 + mt * 16;
        if (out_mode == 3) {
#pragma unroll
            for (int it = 0; it < 8; it++) {
                int linear = it * 32 + lane;
                int row = linear >> 4, f4 = linear & 15;
                float4 v = *(const float4*)&S[row * 68 + f4 * 4];
                *(float4*)&ga.outp[(size_t)(R0 + row) * 512 + C0 + f4 * 4] = v;
            }
        } else {
            int bb = R0 >> 10;
            int l0 = R0 & 1023;
            if (out_mode == 0) {
                int l16 = l0 >> 4;
#pragma unroll
                for (int ks = 0; ks < 8; ks++) {
                    uint4 v;
                    v.x = f2tf(S[g * 68 + ks * 8 + q]);
                    v.y = f2tf(S[(g + 8) * 68 + ks * 8 + q]);
                    v.z = f2tf(S[g * 68 + ks * 8 + q + 4]);
                    v.w = f2tf(S[(g + 8) * 68 + ks * 8 + q + 4]);
                    g_qf[bb][hh][l16][ks][lane] = v;
                }
            } else if (out_mode == 1) {
#pragma unroll
                for (int j = 0; j < 2; j++)
#pragma unroll
                    for (int k16 = 0; k16 < 4; k16++) {
                        int rr = j * 8 + g;
                        uint4 v;
                        v.x = f2tf(S[rr * 68 + k16 * 16 + q]);
                        v.y = f2tf(S[rr * 68 + k16 * 16 + q + 4]);
                        v.z = f2tf(S[rr * 68 + k16 * 16 + q + 8]);
                        v.w = f2tf(S[rr * 68 + k16 * 16 + q + 12]);
                        g_kf[bb][hh][(l0 >> 3) + j][k16][lane] = v;
                    }
            } else {
                int k16v = l0 >> 4;
#pragma unroll
                for (int d8 = 0; d8 < 8; d8++) {
                    uint4 v;
                    v.x = f2tf(S[q * 68 + d8 * 8 + g]);
                    v.y = f2tf(S[(q + 4) * 68 + d8 * 8 + g]);
                    v.z = f2tf(S[(q + 8) * 68 + d8 * 8 + g]);
                    v.w = f2tf(S[(q + 12) * 68 + d8 * 8 + g]);
                    g_vf[bb][hh][k16v][d8][lane] = v;
                }
            }
        }
    }
}

// ---------------- fused flash attention, packed fragments -------------------
#define ASTG 35072

__global__ __launch_bounds__(128) void attn_tf32(const float* __restrict__ pm)
{
    extern __shared__ uint8_t sm[];

    int bh = blockIdx.x;
    int b = bh >> 3, h = bh & 7;
    int tid = threadIdx.x;
    int lane = tid & 31, w = tid >> 5;
    int g = lane >> 2, q = lane & 3;
    int q0 = blockIdx.y * 64;
    int r0 = q0 + w * 16 + g;
    int r1 = r0 + 8;

    auto issue = [&](int t, int stg) {
        uint32_t base = (uint32_t)__cvta_generic_to_shared(sm + stg * ASTG);
        const uint4* kg_ = &g_kf[b][h][t * 8][0][0];
        const uint4* vg_ = &g_vf[b][h][t * 4][0][0];
#pragma unroll
        for (int i = 0; i < 8; i++) {
            int cid = tid + 128 * i;
            cp16(base + cid * 16, kg_ + cid);
            cp16(base + 16384 + cid * 16, vg_ + cid);
        }
        cp16(base + 32768 + tid * 16, (const float*)&g_probs[1][b][h][t * 64][0] + tid * 4);
        if (tid < 16)
            cp16(base + 34816 + tid * 16, pm + (size_t)b * LL + t * 64 + tid * 4);
    };

    uint32_t qa[8][4];
    {
        int l16 = blockIdx.y * 4 + w;
#pragma unroll
        for (int ks = 0; ks < 8; ks++) {
            uint4 t0 = g_qf[b][h][l16][ks][lane];
            qa[ks][0] = t0.x; qa[ks][1] = t0.y; qa[ks][2] = t0.z; qa[ks][3] = t0.w;
        }
    }
    float pq0[8], pq1[8];
#pragma unroll
    for (int c = 0; c < NC; c++) {
        pq0[c] = g_probs[0][b][h][r0][c];
        pq1[c] = g_probs[0][b][h][r1][c];
    }

    float accO[8][4];
#pragma unroll
    for (int nt = 0; nt < 8; nt++)
#pragma unroll
        for (int s = 0; s < 4; s++) accO[nt][s] = 0.f;
    float mrow0 = -1e30f, mrow1 = -1e30f, Z0 = 0.f, Z1 = 0.f;

    issue(0, 0); cp_commit();

    for (int t = 0; t < 16; t++) {
        cp_wait<0>();
        __syncthreads();
        if (t < 15) { issue(t + 1, (t + 1) & 1); cp_commit(); }

        const uint4* Ksm = (const uint4*)(sm + (t & 1) * ASTG);
        const uint4* Vsm = (const uint4*)(sm + (t & 1) * ASTG + 16384);
        const float* pks = (const float*)(sm + (t & 1) * ASTG + 32768);
        const float* padk = (const float*)(sm + (t & 1) * ASTG + 34816);

        float accS[8][4], u[8][4];
#pragma unroll
        for (int nt = 0; nt < 8; nt++) {
#pragma unroll
            for (int j = 0; j < 2; j++) {
                int c = nt * 8 + 2 * q + j;
                float4 pA = *(const float4*)&pks[c * 8];
                float4 pB = *(const float4*)&pks[c * 8 + 4];
                float s0 = pq0[0] * pA.x + pq0[1] * pA.y + pq0[2] * pA.z + pq0[3] * pA.w
                         + pq0[4] * pB.x + pq0[5] * pB.y + pq0[6] * pB.z + pq0[7] * pB.w;
                float s1 = pq1[0] * pA.x + pq1[1] * pA.y + pq1[2] * pA.z + pq1[3] * pA.w
                         + pq1[4] * pB.x + pq1[5] * pB.y + pq1[6] * pB.z + pq1[7] * pB.w;
                float pd = padk[c];
                float cm0 = fminf(fmaxf(1.f - s0 + pd, 0.f), 1.f);
                float cm1 = fminf(fmaxf(1.f - s1 + pd, 0.f), 1.f);
                accS[nt][j]     = -10000.f * cm0; u[nt][j]     = accS[nt][j];
                accS[nt][2 + j] = -10000.f * cm1; u[nt][2 + j] = accS[nt][2 + j];
            }
        }

#pragma unroll
        for (int ks2 = 0; ks2 < 4; ks2++) {
#pragma unroll
            for (int nt = 0; nt < 8; nt++) {
                uint4 kb = Ksm[(nt * 4 + ks2) * 32 + lane];
                mma8(accS[nt], qa[2 * ks2], kb.x, kb.y);
                mma8(accS[nt], qa[2 * ks2 + 1], kb.z, kb.w);
            }
        }

        float t0 = accS[0][0], t1v = accS[0][2];
#pragma unroll
        for (int nt = 0; nt < 8; nt++) {
            t0 = fmaxf(t0, fmaxf(accS[nt][0], accS[nt][1]));
            t1v = fmaxf(t1v, fmaxf(accS[nt][2], accS[nt][3]));
        }
        t0 = fmaxf(t0, __shfl_xor_sync(0xffffffffu, t0, 1));
        t0 = fmaxf(t0, __shfl_xor_sync(0xffffffffu, t0, 2));
        t1v = fmaxf(t1v, __shfl_xor_sync(0xffffffffu, t1v, 1));
        t1v = fmaxf(t1v, __shfl_xor_sync(0xffffffffu, t1v, 2));
        float mn0 = fmaxf(mrow0, t0), mn1 = fmaxf(mrow1, t1v);
        float corr0 = __expf(mrow0 - mn0), corr1 = __expf(mrow1 - mn1);
        mrow0 = mn0; mrow1 = mn1;
        Z0 *= corr0; Z1 *= corr1;
#pragma unroll
        for (int nt = 0; nt < 8; nt++) {
            accO[nt][0] *= corr0; accO[nt][1] *= corr0;
            accO[nt][2] *= corr1; accO[nt][3] *= corr1;
        }
        float z0 = 0.f, z1 = 0.f;
#pragma unroll
        for (int nt = 0; nt < 8; nt++) {
            float e0 = __expf(accS[nt][0] - mn0);
            float e1 = __expf(accS[nt][1] - mn0);
            float e2 = __expf(accS[nt][2] - mn1);
            float e3 = __expf(accS[nt][3] - mn1);
            z0 += e0 + e1; z1 += e2 + e3;
            accS[nt][0] = e0 * (1.f + u[nt][0] * 1e-4f);
            accS[nt][1] = e1 * (1.f + u[nt][1] * 1e-4f);
            accS[nt][2] = e2 * (1.f + u[nt][2] * 1e-4f);
            accS[nt][3] = e3 * (1.f + u[nt][3] * 1e-4f);
        }
        Z0 += z0; Z1 += z1;

        int srcA = (lane & ~3) | (q >> 1);
        int srcB = srcA + 2;
        bool odd = (q & 1);
#pragma unroll
        for (int kg2 = 0; kg2 < 4; kg2++) {
            uint32_t aP[2][4];
#pragma unroll
            for (int half = 0; half < 2; half++) {
                int kg = 2 * kg2 + half;
                float x0 = __shfl_sync(0xffffffffu, accS[kg][0], srcA);
                float x1 = __shfl_sync(0xffffffffu, accS[kg][1], srcA);
                float x4 = __shfl_sync(0xffffffffu, accS[kg][0], srcB);
                float x5 = __shfl_sync(0xffffffffu, accS[kg][1], srcB);
                float y0 = __shfl_sync(0xffffffffu, accS[kg][2], srcA);
                float y1 = __shfl_sync(0xffffffffu, accS[kg][3], srcA);
                float y4 = __shfl_sync(0xffffffffu, accS[kg][2], srcB);
                float y5 = __shfl_sync(0xffffffffu, accS[kg][3], srcB);
                aP[half][0] = f2tf(odd ? x1 : x0);
                aP[half][1] = f2tf(odd ? y1 : y0);
                aP[half][2] = f2tf(odd ? x5 : x4);
                aP[half][3] = f2tf(odd ? y5 : y4);
            }
#pragma unroll
            for (int nt = 0; nt < 8; nt++) {
                uint4 vb = Vsm[(kg2 * 8 + nt) * 32 + lane];
                mma8(accO[nt], aP[0], vb.x, vb.y);
                mma8(accO[nt], aP[1], vb.z, vb.w);
            }
        }
    }

    Z0 += __shfl_xor_sync(0xffffffffu, Z0, 1);
    Z0 += __shfl_xor_sync(0xffffffffu, Z0, 2);
    Z1 += __shfl_xor_sync(0xffffffffu, Z1, 1);
    Z1 += __shfl_xor_sync(0xffffffffu, Z1, 2);
    float iz0 = 1.f / Z0, iz1 = 1.f / Z1;
#pragma unroll
    for (int nt = 0; nt < 8; nt++) {
        float2 o0 = make_float2(accO[nt][0] * iz0, accO[nt][1] * iz0);
        float2 o1 = make_float2(accO[nt][2] * iz1, accO[nt][3] * iz1);
        *(float2*)&g_ctx[b][r0][h * DK + nt * 8 + 2 * q] = o0;
        *(float2*)&g_ctx[b][r1][h * DK + nt * 8 + 2 * q] = o1;
    }
}

// ---------------- finalize ---------------------------------------------------
__global__ void finalize_kernel(float* __restrict__ out, int out_size)
{
    int b = threadIdx.x;
    if (b >= BB) return;
    float kl = 0.f;
    for (int s = 0; s < 2; s++)
        for (int h = 0; h < HH; h++) kl += g_klsum[s][b][h];
    const float c3 = -0.5f * (1.0f + LOG_AV) * (float)DK;
    float kl_total = kl / (float)(HH * LL) + 2.f * c3;

    float dv = 0.f;
    for (int s = 0; s < 2; s++)
        for (int h = 0; h < HH; h++) {
            float frob = 0.f;
            int e = 0;
            for (int c = 0; c < NC; c++)
                for (int c2 = c; c2 < NC; c2++) {
                    float mv = g_M[s][b][h][e++];
                    frob += (c2 == c) ? mv * mv : 2.f * mv * mv;
                }
            dv += 0.75f * (frob - g_dq2[s][b][h]) + 1.25f * g_dm1[s][b][h];
        }
    dv /= (float)HH * (float)LL * (float)LL;

    long base = (long)BB * LL * DMODEL;
    if (out_size >= base + 2 * BB) {
        out[base + b] = kl_total;
        out[base + BB + b] = dv;
    }
}

// ---------------- launch -----------------------------------------------------
extern "C" void kernel_launch(void* const* d_in, const int* in_sizes, int n_in,
                              void* d_out, int out_size)
{
    const float* query  = (const float*)d_in[0];
    const float* key    = (const float*)d_in[1];
    const float* value  = (const float*)d_in[2];
    const float* pmask  = (const float*)d_in[3];
    const float* Wq = (const float*)d_in[4];
    const float* bq = (const float*)d_in[5];
    const float* Wk = (const float*)d_in[6];
    const float* bk = (const float*)d_in[7];
    const float* Wv = (const float*)d_in[8];
    const float* bv = (const float*)d_in[9];
    const float* Wo = (const float*)d_in[10];
    const float* bo = (const float*)d_in[11];
    const float* tok_mu = (const float*)d_in[12];
    const float* tok_lv = (const float*)d_in[13];
    const float* tok_lp = (const float*)d_in[14];
    float* outp = (float*)d_out;

    cudaFuncSetAttribute(gemm_tf32, cudaFuncAttributeMaxDynamicSharedMemorySize, 3 * GSTAGE);
    cudaFuncSetAttribute(attn_tf32, cudaFuncAttributeMaxDynamicSharedMemorySize, 2 * ASTG);

    zero_kernel<<<1, 256>>>();

    PArgs pw;
    pw.W[0] = Wq; pw.W[1] = Wk; pw.W[2] = Wv; pw.W[3] = Wo;
    pack_w<<<1024, 256>>>(pw);

    clustering_kernel<<<dim3(2 * BB * HH, 4), 256>>>(query, key, tok_mu, tok_lv, tok_lp);
    stats_kernel<<<64, 256>>>();

    GArgs qkv;
    qkv.A[0] = query; qkv.A[1] = key; qkv.A[2] = value;
    qkv.Bi[0] = bq;   qkv.Bi[1] = bk; qkv.Bi[2] = bv;
    qkv.sc[0] = 0.125f; qkv.sc[1] = 1.f; qkv.sc[2] = 1.f;
    qkv.md[0] = 0; qkv.md[1] = 1; qkv.md[2] = 2;
    qkv.ws[0] = 0; qkv.ws[1] = 1; qkv.ws[2] = 2;
    qkv.outp = nullptr;
    gemm_tf32<<<dim3(4, 32, 3), 256, 3 * GSTAGE>>>(qkv);

    attn_tf32<<<dim3(BB * HH, LL / 64), 128, 2 * ASTG>>>(pmask);

    GArgs og;
    og.A[0] = nullptr; og.A[1] = nullptr; og.A[2] = nullptr;
    og.Bi[0] = bo; og.Bi[1] = bo; og.Bi[2] = bo;
    og.sc[0] = 1.f; og.sc[1] = 1.f; og.sc[2] = 1.f;
    og.md[0] = 3; og.md[1] = 3; og.md[2] = 3;
    og.ws[0] = 3; og.ws[1] = 3; og.ws[2] = 3;
    og.outp = outp;
    gemm_tf32<<<dim3(4, 32, 1), 256, 3 * GSTAGE>>>(og);

    finalize_kernel<<<1, 32>>>(outp, out_size);
}

// round 6
// speedup vs baseline: 4.8420x; 1.0548x over previous
#include <cuda_runtime.h>
#include <math.h>
#include <stdint.h>

#define BB 4
#define LL 1024
#define DMODEL 512
#define HH 8
#define NC 8
#define DK 64
#define LOG_AV (-4.605170185988091f)   // log(0.01)

// ---------------- scratch (device globals: no allocation allowed) ----------
__device__ __align__(256) float g_probs[2][BB][HH][LL][NC]; // 0=q,1=k
__device__ __align__(256) uint4 g_qf[BB][HH][64][8][32];
__device__ __align__(256) uint4 g_kf[BB][HH][128][4][32];
__device__ __align__(256) uint4 g_vf[BB][HH][64][8][32];
__device__ __align__(256) uint4 g_wf[4][64][32][32];
__device__ __align__(256) float g_ctx[BB][LL][DMODEL];
__device__ float g_M[2][BB][HH][36];
__device__ float g_klsum[2][BB][HH];
__device__ float g_dq2[2][BB][HH];
__device__ float g_dm1[2][BB][HH];

// ---------------- helpers ---------------------------------------------------
__device__ __forceinline__ uint32_t f2tf(float x) {
    uint32_t r;
    asm("cvt.rna.tf32.f32 %0, %1;" : "=r"(r) : "f"(x));
    return r;
}
__device__ __forceinline__ void mma8(float* c, const uint32_t* a, uint32_t b0, uint32_t b1) {
    asm volatile(
        "mma.sync.aligned.m16n8k8.row.col.f32.tf32.tf32.f32 "
        "{%0,%1,%2,%3}, {%4,%5,%6,%7}, {%8,%9}, {%0,%1,%2,%3};"
        : "+f"(c[0]), "+f"(c[1]), "+f"(c[2]), "+f"(c[3])
        : "r"(a[0]), "r"(a[1]), "r"(a[2]), "r"(a[3]), "r"(b0), "r"(b1));
}
__device__ __forceinline__ void cp16(uint32_t saddr, const void* gptr) {
    asm volatile("cp.async.cg.shared.global [%0], [%1], 16;" :: "r"(saddr), "l"(gptr));
}
__device__ __forceinline__ void cp_commit() { asm volatile("cp.async.commit_group;"); }
template<int N> __device__ __forceinline__ void cp_wait() {
    asm volatile("cp.async.wait_group %0;" :: "n"(N));
}

// ---------------- zero accumulators ----------------------------------------
__global__ void zero_kernel() {
    int i = threadIdx.x;
    float* pM = &g_M[0][0][0][0];
    for (int e = i; e < 2 * BB * HH * 36; e += 256) pM[e] = 0.f;
    float* pk = &g_klsum[0][0][0];
    float* pd = &g_dq2[0][0][0];
    float* pm = &g_dm1[0][0][0];
    for (int e = i; e < 2 * BB * HH; e += 256) { pk[e] = 0.f; pd[e] = 0.f; pm[e] = 0.f; }
}

// ---------------- weight pack: W[n][k] -> B-frag tf32 -----------------------
struct PArgs { const float* W[4]; };
__global__ __launch_bounds__(256) void pack_w(PArgs pa) {
    int idx = blockIdx.x * 256 + threadIdx.x;
    int w = idx >> 16;
    int rem = idx & 65535;
    int n8 = rem >> 10;
    int k16 = (rem >> 5) & 31;
    int lane = rem & 31;
    int g = lane >> 2, q = lane & 3;
    const float* src = pa.W[w] + (size_t)(n8 * 8 + g) * 512 + k16 * 16 + q;
    uint4 v;
    v.x = f2tf(src[0]);
    v.y = f2tf(src[4]);
    v.z = f2tf(src[8]);
    v.w = f2tf(src[12]);
    g_wf[w][n8][k16][lane] = v;
}

// ---------------- clustering: probs + kl only (vectorized smem) -------------
__global__ __launch_bounds__(256) void clustering_kernel(
    const float* __restrict__ qin, const float* __restrict__ kin,
    const float* __restrict__ mu, const float* __restrict__ logvar,
    const float* __restrict__ logprior)
{
    __shared__ float4 mu4[NC][16];
    __shared__ float4 iv4[NC][16];
    __shared__ float lvs_s[NC], ratio_s[NC], logp_s[NC], prior_s[NC];

    int bx = blockIdx.x;
    int s = bx >> 5;
    int rem = bx & 31;
    int b = rem >> 3;
    int h = rem & 7;
    int tid = threadIdx.x;
    int l = blockIdx.y * 256 + tid;

    if (tid < NC * 16) {
        int c = tid >> 4, d4 = tid & 15;
        const float* msrc = &mu[(h * NC + c) * DK + d4 * 4];
        const float* lsrc = &logvar[(h * NC + c) * DK + d4 * 4];
        float4 mv = make_float4(msrc[0], msrc[1], msrc[2], msrc[3]);
        float4 ivv = make_float4(expf(-lsrc[0]), expf(-lsrc[1]), expf(-lsrc[2]), expf(-lsrc[3]));
        mu4[c][d4] = mv;
        iv4[c][d4] = ivv;
    }
    __syncthreads();
    if (tid < NC) {
        float ls = 0.f, rs = 0.f;
        const float avar = expf(LOG_AV);
        for (int d4 = 0; d4 < 16; d4++) {
            float4 ivv = iv4[tid][d4];
            rs += ivv.x + ivv.y + ivv.z + ivv.w;
        }
        for (int d = 0; d < DK; d++)
            ls += logvar[(h * NC + tid) * DK + d];
        lvs_s[tid] = ls;
        ratio_s[tid] = avar * rs;
    }
    if (tid == 0) {
        float mx = -1e30f;
        for (int c = 0; c < NC; c++) mx = fmaxf(mx, logprior[h * NC + c]);
        float ss = 0.f;
        for (int c = 0; c < NC; c++) ss += expf(logprior[h * NC + c] - mx);
        float lse = mx + logf(ss);
        for (int c = 0; c < NC; c++) {
            logp_s[c] = logprior[h * NC + c] - lse;
            prior_s[c] = expf(logp_s[c]);
        }
    }
    __syncthreads();

    const float* src = (s == 0) ? qin : kin;
    const float4* xr4 = (const float4*)(src + ((size_t)b * LL + l) * DMODEL + h * DK);

    float4 x4[16];
#pragma unroll
    for (int dd = 0; dd < 16; dd++) x4[dd] = xr4[dd];

    float mse[NC], logit[NC];
#pragma unroll
    for (int c = 0; c < NC; c++) {
        float a = 0.f;
#pragma unroll
        for (int d4 = 0; d4 < 16; d4++) {
            float4 mv = mu4[c][d4];
            float4 ivv = iv4[c][d4];
            float t0 = x4[d4].x - mv.x; a = fmaf(t0 * t0, ivv.x, a);
            float t1 = x4[d4].y - mv.y; a = fmaf(t1 * t1, ivv.y, a);
            float t2 = x4[d4].z - mv.z; a = fmaf(t2 * t2, ivv.z, a);
            float t3 = x4[d4].w - mv.w; a = fmaf(t3 * t3, ivv.w, a);
        }
        mse[c] = a;
        logit[c] = -0.5f * a - 0.5f * lvs_s[c] + logp_s[c];
    }
    float m = logit[0];
#pragma unroll
    for (int c = 1; c < NC; c++) m = fmaxf(m, logit[c]);
    float p[NC];
    float Zl = 0.f;
#pragma unroll
    for (int c = 0; c < NC; c++) { p[c] = expf(logit[c] - m); Zl += p[c]; }
    float lz = logf(Zl);
    float inv = 1.f / Zl;

    float t1 = 0.f;
#pragma unroll
    for (int c = 0; c < NC; c++)
        t1 += prior_s[c] * (logp_s[c] - (logit[c] - m - lz));
#pragma unroll
    for (int c = 0; c < NC; c++) p[c] *= inv;
    float t2 = 0.f;
#pragma unroll
    for (int c = 0; c < NC; c++)
        t2 += p[c] * (mse[c] + ratio_s[c] + lvs_s[c]);
    float klloc = t1 + 0.5f * t2;

#pragma unroll
    for (int c = 0; c < NC; c++) g_probs[s][b][h][l][c] = p[c];

    float v = klloc;
    v += __shfl_xor_sync(0xffffffffu, v, 16);
    v += __shfl_xor_sync(0xffffffffu, v, 8);
    v += __shfl_xor_sync(0xffffffffu, v, 4);
    v += __shfl_xor_sync(0xffffffffu, v, 2);
    v += __shfl_xor_sync(0xffffffffu, v, 1);
    if ((tid & 31) == 0) atomicAdd(&g_klsum[s][b][h], v);
}

// ---------------- stats: M = P^T P upper-tri, dq2, dm1 ----------------------
__global__ __launch_bounds__(256) void stats_kernel()
{
    int sbh = blockIdx.x >> 2;               // 0..63
    int chunk = blockIdx.x & 3;
    int s = sbh >> 5, b = (sbh >> 3) & 3, h = sbh & 7;
    int tid = threadIdx.x;
    int l = chunk * 256 + tid;

    float4 pA = *(const float4*)&g_probs[s][b][h][l][0];
    float4 pB = *(const float4*)&g_probs[s][b][h][l][4];
    float p[8] = { pA.x, pA.y, pA.z, pA.w, pB.x, pB.y, pB.z, pB.w };
    float dq = 0.f;
#pragma unroll
    for (int c = 0; c < 8; c++) dq = fmaf(p[c], p[c], dq);
    float dq2 = dq * dq;
    float dm1 = (dq - 1.f) * (dq - 1.f);
    float M[36];
    {
        int e = 0;
#pragma unroll
        for (int c = 0; c < 8; c++)
#pragma unroll
            for (int c2 = c; c2 < 8; c2++) M[e++] = p[c] * p[c2];
    }

#pragma unroll
    for (int e = 0; e < 36; e++) {
        float v = M[e];
        v += __shfl_xor_sync(0xffffffffu, v, 16);
        v += __shfl_xor_sync(0xffffffffu, v, 8);
        v += __shfl_xor_sync(0xffffffffu, v, 4);
        v += __shfl_xor_sync(0xffffffffu, v, 2);
        v += __shfl_xor_sync(0xffffffffu, v, 1);
        if ((tid & 31) == 0) atomicAdd(&g_M[s][b][h][e], v);
    }
    float v2[2] = { dq2, dm1 };
    float* d2[2] = { &g_dq2[s][b][h], &g_dm1[s][b][h] };
#pragma unroll
    for (int e = 0; e < 2; e++) {
        float v = v2[e];
        v += __shfl_xor_sync(0xffffffffu, v, 16);
        v += __shfl_xor_sync(0xffffffffu, v, 8);
        v += __shfl_xor_sync(0xffffffffu, v, 4);
        v += __shfl_xor_sync(0xffffffffu, v, 2);
        v += __shfl_xor_sync(0xffffffffu, v, 1);
        if ((tid & 31) == 0) atomicAdd(d2[e], v);
    }
}

// ---------------- cp.async 3-stage tf32 GEMM, packed-W ----------------------
#define GSTR 20
#define GSTAGE 18432
struct GArgs {
    const float* A[3];
    const float* Bi[3];
    float sc[3];
    int md[3];
    int ws[3];
    float* outp;
};

__global__ __launch_bounds__(256, 2) void gemm_tf32(GArgs ga)
{
    extern __shared__ uint8_t sm[];
    int z = blockIdx.z;
    const float* Ap = ga.A[z];
    if (!Ap) Ap = &g_ctx[0][0][0];
    const float* bias = ga.Bi[z];
    float scale = ga.sc[z];
    int out_mode = ga.md[z];
    int wsel = ga.ws[z];

    int tid = threadIdx.x;
    int lane = tid & 31, wid = tid >> 5;
    int g = lane >> 2, q = lane & 3;
    int wm = wid & 3, wn = wid >> 2;
    int m0 = blockIdx.y * 128, n0 = blockIdx.x * 128;
    int n8base = n0 >> 3;

    auto issue = [&](int kc, int stg) {
        uint32_t base = (uint32_t)__cvta_generic_to_shared(sm + stg * GSTAGE);
#pragma unroll
        for (int i = 0; i < 2; i++) {
            int cid = tid + 256 * i;
            int row = cid >> 2, c = cid & 3;
            cp16(base + (row * GSTR + c * 4) * 4,
                 Ap + (size_t)(m0 + row) * 512 + kc * 16 + c * 4);
            int n8b = cid >> 5, ln = cid & 31;
            cp16(base + 10240 + cid * 16, &g_wf[wsel][n8base + n8b][kc][ln]);
        }
    };

    float acc[2][8][4];
#pragma unroll
    for (int mt = 0; mt < 2; mt++)
#pragma unroll
        for (int nt = 0; nt < 8; nt++)
#pragma unroll
            for (int s = 0; s < 4; s++) acc[mt][nt][s] = 0.f;

    issue(0, 0); cp_commit();
    issue(1, 1); cp_commit();

    for (int kc = 0; kc < 32; kc++) {
        if (kc < 31) cp_wait<1>(); else cp_wait<0>();
        __syncthreads();
        if (kc + 2 < 32) { issue(kc + 2, (kc + 2) % 3); cp_commit(); }

        const float* As = (const float*)(sm + (kc % 3) * GSTAGE);
        const uint4* Bsm = (const uint4*)(sm + (kc % 3) * GSTAGE + 10240);

        uint4 bfr[8];
#pragma unroll
        for (int nt = 0; nt < 8; nt++)
            bfr[nt] = Bsm[(wn * 8 + nt) * 32 + lane];

#pragma unroll
        for (int ks = 0; ks < 2; ks++) {
            uint32_t a[2][4];
#pragma unroll
            for (int mt = 0; mt < 2; mt++) {
                int mr = wm * 32 + mt * 16;
                a[mt][0] = f2tf(As[(mr + g) * GSTR + ks * 8 + q]);
                a[mt][1] = f2tf(As[(mr + g + 8) * GSTR + ks * 8 + q]);
                a[mt][2] = f2tf(As[(mr + g) * GSTR + ks * 8 + q + 4]);
                a[mt][3] = f2tf(As[(mr + g + 8) * GSTR + ks * 8 + q + 4]);
            }
#pragma unroll
            for (int nt = 0; nt < 8; nt++) {
                uint32_t b0 = ks ? bfr[nt].z : bfr[nt].x;
                uint32_t b1 = ks ? bfr[nt].w : bfr[nt].y;
                mma8(acc[0][nt], a[0], b0, b1);
                mma8(acc[1][nt], a[1], b0, b1);
            }
        }
    }

    // ---------- staged epilogue: smem transpose -> coalesced STG.128 -------
    __syncthreads();
    float* S = (float*)sm + wid * 1088;      // 16 x 68 floats per warp
    int C0 = n0 + wn * 64;
    int hh = C0 >> 6;

#pragma unroll
    for (int mt = 0; mt < 2; mt++) {
        if (mt) __syncwarp();
#pragma unroll
        for (int nt = 0; nt < 8; nt++)
#pragma unroll
            for (int s = 0; s < 4; s++) {
                int r = g + ((s >= 2) ? 8 : 0);
                int ct = nt * 8 + 2 * q + (s & 1);
                S[r * 68 + ct] = (acc[mt][nt][s] + bias[C0 + ct]) * scale;
            }
        __syncwarp();

        int R0 = m0 + wm * 32 + mt * 16;
        if (out_mode == 3) {
#pragma unroll
            for (int it = 0; it < 8; it++) {
                int linear = it * 32 + lane;
                int row = linear >> 4, f4 = linear & 15;
                float4 v = *(const float4*)&S[row * 68 + f4 * 4];
                *(float4*)&ga.outp[(size_t)(R0 + row) * 512 + C0 + f4 * 4] = v;
            }
        } else {
            int bb = R0 >> 10;
            int l0 = R0 & 1023;
            if (out_mode == 0) {
                int l16 = l0 >> 4;
#pragma unroll
                for (int ks = 0; ks < 8; ks++) {
                    uint4 v;
                    v.x = f2tf(S[g * 68 + ks * 8 + q]);
                    v.y = f2tf(S[(g + 8) * 68 + ks * 8 + q]);
                    v.z = f2tf(S[g * 68 + ks * 8 + q + 4]);
                    v.w = f2tf(S[(g + 8) * 68 + ks * 8 + q + 4]);
                    g_qf[bb][hh][l16][ks][lane] = v;
                }
            } else if (out_mode == 1) {
#pragma unroll
                for (int j = 0; j < 2; j++)
#pragma unroll
                    for (int k16 = 0; k16 < 4; k16++) {
                        int rr = j * 8 + g;
                        uint4 v;
                        v.x = f2tf(S[rr * 68 + k16 * 16 + q]);
                        v.y = f2tf(S[rr * 68 + k16 * 16 + q + 4]);
                        v.z = f2tf(S[rr * 68 + k16 * 16 + q + 8]);
                        v.w = f2tf(S[rr * 68 + k16 * 16 + q + 12]);
                        g_kf[bb][hh][(l0 >> 3) + j][k16][lane] = v;
                    }
            } else {
                int k16v = l0 >> 4;
#pragma unroll
                for (int d8 = 0; d8 < 8; d8++) {
                    uint4 v;
                    v.x = f2tf(S[q * 68 + d8 * 8 + g]);
                    v.y = f2tf(S[(q + 4) * 68 + d8 * 8 + g]);
                    v.z = f2tf(S[(q + 8) * 68 + d8 * 8 + g]);
                    v.w = f2tf(S[(q + 12) * 68 + d8 * 8 + g]);
                    g_vf[bb][hh][k16v][d8][lane] = v;
                }
            }
        }
    }
}

// ---------------- fused flash attention, packed fragments -------------------
#define ASTG 35072

__global__ __launch_bounds__(128) void attn_tf32(const float* __restrict__ pm)
{
    extern __shared__ uint8_t sm[];

    int bh = blockIdx.x;
    int b = bh >> 3, h = bh & 7;
    int tid = threadIdx.x;
    int lane = tid & 31, w = tid >> 5;
    int g = lane >> 2, q = lane & 3;
    int q0 = blockIdx.y * 64;
    int r0 = q0 + w * 16 + g;
    int r1 = r0 + 8;

    auto issue = [&](int t, int stg) {
        uint32_t base = (uint32_t)__cvta_generic_to_shared(sm + stg * ASTG);
        const uint4* kg_ = &g_kf[b][h][t * 8][0][0];
        const uint4* vg_ = &g_vf[b][h][t * 4][0][0];
#pragma unroll
        for (int i = 0; i < 8; i++) {
            int cid = tid + 128 * i;
            cp16(base + cid * 16, kg_ + cid);
            cp16(base + 16384 + cid * 16, vg_ + cid);
        }
        cp16(base + 32768 + tid * 16, (const float*)&g_probs[1][b][h][t * 64][0] + tid * 4);
        if (tid < 16)
            cp16(base + 34816 + tid * 16, pm + (size_t)b * LL + t * 64 + tid * 4);
    };

    uint32_t qa[8][4];
    {
        int l16 = blockIdx.y * 4 + w;
#pragma unroll
        for (int ks = 0; ks < 8; ks++) {
            uint4 t0 = g_qf[b][h][l16][ks][lane];
            qa[ks][0] = t0.x; qa[ks][1] = t0.y; qa[ks][2] = t0.z; qa[ks][3] = t0.w;
        }
    }
    float pq0[8], pq1[8];
#pragma unroll
    for (int c = 0; c < NC; c++) {
        pq0[c] = g_probs[0][b][h][r0][c];
        pq1[c] = g_probs[0][b][h][r1][c];
    }

    float accO[8][4];
#pragma unroll
    for (int nt = 0; nt < 8; nt++)
#pragma unroll
        for (int s = 0; s < 4; s++) accO[nt][s] = 0.f;
    float mrow0 = -1e30f, mrow1 = -1e30f, Z0 = 0.f, Z1 = 0.f;

    issue(0, 0); cp_commit();

    for (int t = 0; t < 16; t++) {
        cp_wait<0>();
        __syncthreads();
        if (t < 15) { issue(t + 1, (t + 1) & 1); cp_commit(); }

        const uint4* Ksm = (const uint4*)(sm + (t & 1) * ASTG);
        const uint4* Vsm = (const uint4*)(sm + (t & 1) * ASTG + 16384);
        const float* pks = (const float*)(sm + (t & 1) * ASTG + 32768);
        const float* padk = (const float*)(sm + (t & 1) * ASTG + 34816);

        float accS[8][4], u[8][4];
#pragma unroll
        for (int nt = 0; nt < 8; nt++) {
#pragma unroll
            for (int j = 0; j < 2; j++) {
                int c = nt * 8 + 2 * q + j;
                float4 pA = *(const float4*)&pks[c * 8];
                float4 pB = *(const float4*)&pks[c * 8 + 4];
                float s0 = pq0[0] * pA.x + pq0[1] * pA.y + pq0[2] * pA.z + pq0[3] * pA.w
                         + pq0[4] * pB.x + pq0[5] * pB.y + pq0[6] * pB.z + pq0[7] * pB.w;
                float s1 = pq1[0] * pA.x + pq1[1] * pA.y + pq1[2] * pA.z + pq1[3] * pA.w
                         + pq1[4] * pB.x + pq1[5] * pB.y + pq1[6] * pB.z + pq1[7] * pB.w;
                float pd = padk[c];
                float cm0 = fminf(fmaxf(1.f - s0 + pd, 0.f), 1.f);
                float cm1 = fminf(fmaxf(1.f - s1 + pd, 0.f), 1.f);
                accS[nt][j]     = -10000.f * cm0; u[nt][j]     = accS[nt][j];
                accS[nt][2 + j] = -10000.f * cm1; u[nt][2 + j] = accS[nt][2 + j];
            }
        }

#pragma unroll
        for (int ks2 = 0; ks2 < 4; ks2++) {
#pragma unroll
            for (int nt = 0; nt < 8; nt++) {
                uint4 kb = Ksm[(nt * 4 + ks2) * 32 + lane];
                mma8(accS[nt], qa[2 * ks2], kb.x, kb.y);
                mma8(accS[nt], qa[2 * ks2 + 1], kb.z, kb.w);
            }
        }

        float t0 = accS[0][0], t1v = accS[0][2];
#pragma unroll
        for (int nt = 0; nt < 8; nt++) {
            t0 = fmaxf(t0, fmaxf(accS[nt][0], accS[nt][1]));
            t1v = fmaxf(t1v, fmaxf(accS[nt][2], accS[nt][3]));
        }
        t0 = fmaxf(t0, __shfl_xor_sync(0xffffffffu, t0, 1));
        t0 = fmaxf(t0, __shfl_xor_sync(0xffffffffu, t0, 2));
        t1v = fmaxf(t1v, __shfl_xor_sync(0xffffffffu, t1v, 1));
        t1v = fmaxf(t1v, __shfl_xor_sync(0xffffffffu, t1v, 2));
        float mn0 = fmaxf(mrow0, t0), mn1 = fmaxf(mrow1, t1v);
        float corr0 = __expf(mrow0 - mn0), corr1 = __expf(mrow1 - mn1);
        mrow0 = mn0; mrow1 = mn1;
        Z0 *= corr0; Z1 *= corr1;
#pragma unroll
        for (int nt = 0; nt < 8; nt++) {
            accO[nt][0] *= corr0; accO[nt][1] *= corr0;
            accO[nt][2] *= corr1; accO[nt][3] *= corr1;
        }
        float z0 = 0.f, z1 = 0.f;
#pragma unroll
        for (int nt = 0; nt < 8; nt++) {
            float e0 = __expf(accS[nt][0] - mn0);
            float e1 = __expf(accS[nt][1] - mn0);
            float e2 = __expf(accS[nt][2] - mn1);
            float e3 = __expf(accS[nt][3] - mn1);
            z0 += e0 + e1; z1 += e2 + e3;
            accS[nt][0] = e0 * (1.f + u[nt][0] * 1e-4f);
            accS[nt][1] = e1 * (1.f + u[nt][1] * 1e-4f);
            accS[nt][2] = e2 * (1.f + u[nt][2] * 1e-4f);
            accS[nt][3] = e3 * (1.f + u[nt][3] * 1e-4f);
        }
        Z0 += z0; Z1 += z1;

        int srcA = (lane & ~3) | (q >> 1);
        int srcB = srcA + 2;
        bool odd = (q & 1);
#pragma unroll
        for (int kg2 = 0; kg2 < 4; kg2++) {
            uint32_t aP[2][4];
#pragma unroll
            for (int half = 0; half < 2; half++) {
                int kg = 2 * kg2 + half;
                float x0 = __shfl_sync(0xffffffffu, accS[kg][0], srcA);
                float x1 = __shfl_sync(0xffffffffu, accS[kg][1], srcA);
                float x4 = __shfl_sync(0xffffffffu, accS[kg][0], srcB);
                float x5 = __shfl_sync(0xffffffffu, accS[kg][1], srcB);
                float y0 = __shfl_sync(0xffffffffu, accS[kg][2], srcA);
                float y1 = __shfl_sync(0xffffffffu, accS[kg][3], srcA);
                float y4 = __shfl_sync(0xffffffffu, accS[kg][2], srcB);
                float y5 = __shfl_sync(0xffffffffu, accS[kg][3], srcB);
                aP[half][0] = f2tf(odd ? x1 : x0);
                aP[half][1] = f2tf(odd ? y1 : y0);
                aP[half][2] = f2tf(odd ? x5 : x4);
                aP[half][3] = f2tf(odd ? y5 : y4);
            }
#pragma unroll
            for (int nt = 0; nt < 8; nt++) {
                uint4 vb = Vsm[(kg2 * 8 + nt) * 32 + lane];
                mma8(accO[nt], aP[0], vb.x, vb.y);
                mma8(accO[nt], aP[1], vb.z, vb.w);
            }
        }
    }

    Z0 += __shfl_xor_sync(0xffffffffu, Z0, 1);
    Z0 += __shfl_xor_sync(0xffffffffu, Z0, 2);
    Z1 += __shfl_xor_sync(0xffffffffu, Z1, 1);
    Z1 += __shfl_xor_sync(0xffffffffu, Z1, 2);
    float iz0 = 1.f / Z0, iz1 = 1.f / Z1;
#pragma unroll
    for (int nt = 0; nt < 8; nt++) {
        float2 o0 = make_float2(accO[nt][0] * iz0, accO[nt][1] * iz0);
        float2 o1 = make_float2(accO[nt][2] * iz1, accO[nt][3] * iz1);
        *(float2*)&g_ctx[b][r0][h * DK + nt * 8 + 2 * q] = o0;
        *(float2*)&g_ctx[b][r1][h * DK + nt * 8 + 2 * q] = o1;
    }
}

// ---------------- finalize ---------------------------------------------------
__global__ void finalize_kernel(float* __restrict__ out, int out_size)
{
    int b = threadIdx.x;
    if (b >= BB) return;
    float kl = 0.f;
    for (int s = 0; s < 2; s++)
        for (int h = 0; h < HH; h++) kl += g_klsum[s][b][h];
    const float c3 = -0.5f * (1.0f + LOG_AV) * (float)DK;
    float kl_total = kl / (float)(HH * LL) + 2.f * c3;

    float dv = 0.f;
    for (int s = 0; s < 2; s++)
        for (int h = 0; h < HH; h++) {
            float frob = 0.f;
            int e = 0;
            for (int c = 0; c < NC; c++)
                for (int c2 = c; c2 < NC; c2++) {
                    float mv = g_M[s][b][h][e++];
                    frob += (c2 == c) ? mv * mv : 2.f * mv * mv;
                }
            dv += 0.75f * (frob - g_dq2[s][b][h]) + 1.25f * g_dm1[s][b][h];
        }
    dv /= (float)HH * (float)LL * (float)LL;

    long base = (long)BB * LL * DMODEL;
    if (out_size >= base + 2 * BB) {
        out[base + b] = kl_total;
        out[base + BB + b] = dv;
    }
}

// ---------------- launch -----------------------------------------------------
extern "C" void kernel_launch(void* const* d_in, const int* in_sizes, int n_in,
                              void* d_out, int out_size)
{
    const float* query  = (const float*)d_in[0];
    const float* key    = (const float*)d_in[1];
    const float* value  = (const float*)d_in[2];
    const float* pmask  = (const float*)d_in[3];
    const float* Wq = (const float*)d_in[4];
    const float* bq = (const float*)d_in[5];
    const float* Wk = (const float*)d_in[6];
    const float* bk = (const float*)d_in[7];
    const float* Wv = (const float*)d_in[8];
    const float* bv = (const float*)d_in[9];
    const float* Wo = (const float*)d_in[10];
    const float* bo = (const float*)d_in[11];
    const float* tok_mu = (const float*)d_in[12];
    const float* tok_lv = (const float*)d_in[13];
    const float* tok_lp = (const float*)d_in[14];
    float* outp = (float*)d_out;

    cudaFuncSetAttribute(gemm_tf32, cudaFuncAttributeMaxDynamicSharedMemorySize, 3 * GSTAGE);
    cudaFuncSetAttribute(attn_tf32, cudaFuncAttributeMaxDynamicSharedMemorySize, 2 * ASTG);

    // fork-join: side stream runs clustering+stats concurrently with
    // pack_w + QKV gemm. Created fresh per call (deterministic work); not
    // destroyed to avoid invalidating an in-flight capture.
    cudaStream_t sB;
    cudaStreamCreateWithFlags(&sB, cudaStreamNonBlocking);
    cudaEvent_t evFork, evJoin;
    cudaEventCreateWithFlags(&evFork, cudaEventDisableTiming);
    cudaEventCreateWithFlags(&evJoin, cudaEventDisableTiming);

    zero_kernel<<<1, 256>>>();
    cudaEventRecord(evFork, 0);
    cudaStreamWaitEvent(sB, evFork, 0);

    // branch B: clustering -> stats
    clustering_kernel<<<dim3(2 * BB * HH, 4), 256, 0, sB>>>(query, key, tok_mu, tok_lv, tok_lp);
    stats_kernel<<<256, 256, 0, sB>>>();
    cudaEventRecord(evJoin, sB);

    // branch A: pack -> QKV gemm
    PArgs pw;
    pw.W[0] = Wq; pw.W[1] = Wk; pw.W[2] = Wv; pw.W[3] = Wo;
    pack_w<<<1024, 256>>>(pw);

    GArgs qkv;
    qkv.A[0] = query; qkv.A[1] = key; qkv.A[2] = value;
    qkv.Bi[0] = bq;   qkv.Bi[1] = bk; qkv.Bi[2] = bv;
    qkv.sc[0] = 0.125f; qkv.sc[1] = 1.f; qkv.sc[2] = 1.f;
    qkv.md[0] = 0; qkv.md[1] = 1; qkv.md[2] = 2;
    qkv.ws[0] = 0; qkv.ws[1] = 1; qkv.ws[2] = 2;
    qkv.outp = nullptr;
    gemm_tf32<<<dim3(4, 32, 3), 256, 3 * GSTAGE>>>(qkv);

    // join: attn needs probs (B) + q/k/v fragments (A)
    cudaStreamWaitEvent(0, evJoin, 0);

    attn_tf32<<<dim3(BB * HH, LL / 64), 128, 2 * ASTG>>>(pmask);

    GArgs og;
    og.A[0] = nullptr; og.A[1] = nullptr; og.A[2] = nullptr;
    og.Bi[0] = bo; og.Bi[1] = bo; og.Bi[2] = bo;
    og.sc[0] = 1.f; og.sc[1] = 1.f; og.sc[2] = 1.f;
    og.md[0] = 3; og.md[1] = 3; og.md[2] = 3;
    og.ws[0] = 3; og.ws[1] = 3; og.ws[2] = 3;
    og.outp = outp;
    gemm_tf32<<<dim3(4, 32, 1), 256, 3 * GSTAGE>>>(og);

    finalize_kernel<<<1, 32>>>(outp, out_size);
}